// round 3
// baseline (speedup 1.0000x reference)
#include <cuda_runtime.h>
#include <cuda_bf16.h>
#include <cstdint>

// ---------------- problem constants ----------------
#define BB   32
#define CC   128
#define HH   64
#define WW   64
#define DD   256
#define FF_  512
#define HWN  4096          // H*W = 4096 = patch cols per batch too
#define EPS  1e-5f

// ---------------- static scratch ----------------
__device__ float g_y [ (size_t)BB * CC  * HWN ];   // 64 MB  dwconv out
__device__ float g_p [ (size_t)BB * DD  * HWN ];   // 128 MB token tensor
__device__ float g_kv[ (size_t)BB * 512 * HWN ];   // 256 MB k(0..255) v(256..511)
__device__ float g_h [ (size_t)BB * 512 * HWN ];   // 256 MB ffn hidden
__device__ float g_mean[ BB * HWN ];
__device__ float g_rstd[ BB * HWN ];
__device__ float g_ctx [ BB * 4 * DD ];
__device__ float g_s2[CC], g_b2[CC];

// ---------------- packed f32x2 helpers ----------------
#define FFMA2(d, a, b) \
    asm("fma.rn.f32x2 %0, %1, %2, %0;" : "+l"(d) : "l"(a), "l"(b))

__device__ __forceinline__ unsigned long long pack_dup(float x) {
    unsigned long long r;
    asm("mov.b64 %0, {%1, %1};" : "=l"(r) : "r"(__float_as_uint(x)));
    return r;
}

// ---------------- prep: fold BN2 ----------------
__global__ void prep_k(const float* __restrict__ g, const float* __restrict__ b,
                       const float* __restrict__ m, const float* __restrict__ v)
{
    int i = threadIdx.x;
    if (i < CC) {
        float s = g[i] * rsqrtf(v[i] + EPS);
        g_s2[i] = s;
        g_b2[i] = b[i] - m[i] * s;
    }
}

// ---------------- dwconv3x3 + BN1 + leaky ----------------
__global__ void __launch_bounds__(256) dwconv_k(
    const float* __restrict__ x, const float* __restrict__ w,
    const float* __restrict__ bg, const float* __restrict__ bbias,
    const float* __restrict__ bm, const float* __restrict__ bv)
{
    int b = blockIdx.z, c = blockIdx.y;
    int idx = blockIdx.x * 256 + threadIdx.x;      // 0..4095 pixel in plane
    __shared__ float ws[9];
    __shared__ float sc, sh;
    if (threadIdx.x < 9) ws[threadIdx.x] = w[c * 9 + threadIdx.x];
    if (threadIdx.x == 0) {
        float s = bg[c] * rsqrtf(bv[c] + EPS);
        sc = s; sh = bbias[c] - bm[c] * s;
    }
    __syncthreads();
    int h = idx >> 6, wq = idx & 63;
    const float* xp = x + ((size_t)b * CC + c) * HWN;
    float acc = 0.f;
#pragma unroll
    for (int dh = 0; dh < 3; dh++) {
        int hh = h + dh - 1;
        if (hh < 0 || hh >= HH) continue;
#pragma unroll
        for (int dw = 0; dw < 3; dw++) {
            int ww2 = wq + dw - 1;
            if (ww2 < 0 || ww2 >= WW) continue;
            acc = fmaf(xp[hh * 64 + ww2], ws[dh * 3 + dw], acc);
        }
    }
    float o = acc * sc + sh;
    o = (o > 0.f) ? o : 0.1f * o;
    g_y[((size_t)b * CC + c) * HWN + idx] = o;
}

// ---------------- per-column mean / rstd over D=256 ----------------
__global__ void colstats_k(const float* __restrict__ p)
{
    int b   = blockIdx.y;
    int col = blockIdx.x * 32 + threadIdx.x;
    int ty  = threadIdx.y;
    size_t base = (size_t)b * DD * HWN + col;
    float s = 0.f, s2 = 0.f;
    for (int d = ty; d < DD; d += 8) {
        float v = p[base + ((size_t)d << 12)];
        s += v; s2 = fmaf(v, v, s2);
    }
    __shared__ float sh1[8][32], sh2[8][32];
    sh1[ty][threadIdx.x] = s; sh2[ty][threadIdx.x] = s2;
    __syncthreads();
    if (ty == 0) {
        float a = 0.f, a2 = 0.f;
#pragma unroll
        for (int k = 0; k < 8; k++) { a += sh1[k][threadIdx.x]; a2 += sh2[k][threadIdx.x]; }
        float mean = a * (1.f / DD);
        float var  = a2 * (1.f / DD) - mean * mean;
        g_mean[b * HWN + col] = mean;
        g_rstd[b * HWN + col] = rsqrtf(var + EPS);
    }
}

// ---------------- fused q-GEMV + softmax + ctx ----------------
__global__ void __launch_bounds__(256) qsoftctx_k(
    const float* __restrict__ p,
    const float* __restrict__ lng, const float* __restrict__ lnb,
    const float* __restrict__ wq,  const float* __restrict__ qb)
{
    __shared__ float sprob[1024];
    __shared__ float wqs[256], gs[256], bs[256];
    __shared__ float red[256];
    int tid = threadIdx.x;
    int b = blockIdx.x >> 2, pq = blockIdx.x & 3;
    wqs[tid] = wq[tid]; gs[tid] = lng[tid]; bs[tid] = lnb[tid];
    __syncthreads();
    size_t pbase = (size_t)b * DD * HWN + pq * 1024;
    int cb = b * HWN + pq * 1024;
    float q0 = qb[0];
    float qv[4];
#pragma unroll
    for (int r = 0; r < 4; r++) {
        int n = tid + (r << 8);
        float m_ = g_mean[cb + n], rs_ = g_rstd[cb + n];
        float acc = q0;
#pragma unroll 4
        for (int k = 0; k < 256; k++) {
            float z = (p[pbase + ((size_t)k << 12) + n] - m_) * rs_ * gs[k] + bs[k];
            acc = fmaf(wqs[k], z, acc);
        }
        qv[r] = acc;
    }
    // block max
    float lm = fmaxf(fmaxf(qv[0], qv[1]), fmaxf(qv[2], qv[3]));
    red[tid] = lm; __syncthreads();
    for (int s = 128; s > 0; s >>= 1) { if (tid < s) red[tid] = fmaxf(red[tid], red[tid + s]); __syncthreads(); }
    float gm = red[0]; __syncthreads();
    float e[4]; float ls = 0.f;
#pragma unroll
    for (int r = 0; r < 4; r++) { e[r] = __expf(qv[r] - gm); ls += e[r]; }
    red[tid] = ls; __syncthreads();
    for (int s = 128; s > 0; s >>= 1) { if (tid < s) red[tid] += red[tid + s]; __syncthreads(); }
    float inv = 1.f / red[0];
#pragma unroll
    for (int r = 0; r < 4; r++) sprob[tid + (r << 8)] = e[r] * inv;
    __syncthreads();
    // ctx[d] = sum_n k[d,n] * prob[n]   (k rows are g_kv rows 0..255)
    int warp = tid >> 5, lane = tid & 31;
    for (int d = warp; d < 256; d += 8) {
        const float* kr = g_kv + ((size_t)b * 512 + d) * HWN + pq * 1024;
        float acc = 0.f;
#pragma unroll 8
        for (int n = lane; n < 1024; n += 32) acc = fmaf(kr[n], sprob[n], acc);
#pragma unroll
        for (int o = 16; o > 0; o >>= 1) acc += __shfl_down_sync(0xffffffffu, acc, o);
        if (lane == 0) g_ctx[(b << 10) + (pq << 8) + d] = acc;
    }
}

// ---------------- templated SGEMM (FFMA2, double-buffered) ----------------
// Y[b, m, col] = sum_k W[m,k] * T(X[b, k, col]) ;  per-batch X stride = strideX
enum { BT_NONE = 0, BT_LN = 1, BT_RELUCTX = 2 };
enum { EP_STORE = 0, EP_LEAKY = 1, EP_RESID = 2, EP_PERM_P = 3, EP_PERM_OUT = 4 };

template<int BT>
__device__ __forceinline__ void bt_xform(float4& bv, int kg, int cb, int ctxb,
                                         const float* __restrict__ lng,
                                         const float* __restrict__ lnb,
                                         int bCol)
{
    if (BT == BT_LN) {
        float gk = lng[kg], bk = lnb[kg];
        int c = cb + bCol;
        bv.x = (bv.x - g_mean[c + 0]) * g_rstd[c + 0] * gk + bk;
        bv.y = (bv.y - g_mean[c + 1]) * g_rstd[c + 1] * gk + bk;
        bv.z = (bv.z - g_mean[c + 2]) * g_rstd[c + 2] * gk + bk;
        bv.w = (bv.w - g_mean[c + 3]) * g_rstd[c + 3] * gk + bk;
    } else if (BT == BT_RELUCTX) {
        float cv = g_ctx[ctxb + kg];
        bv.x = fmaxf(bv.x, 0.f) * cv; bv.y = fmaxf(bv.y, 0.f) * cv;
        bv.z = fmaxf(bv.z, 0.f) * cv; bv.w = fmaxf(bv.w, 0.f) * cv;
    }
}

template<int BT, int EP>
__global__ void __launch_bounds__(256, 2) gemm_k(
    const float* __restrict__ W, const float* __restrict__ X,
    float* __restrict__ Y, const float* __restrict__ bias,
    const float* __restrict__ lng, const float* __restrict__ lnb,
    int M, int K, long strideX)
{
    const int b    = blockIdx.z;
    const int colT = blockIdx.x * 128;
    const int rowT = blockIdx.y * 128;
    const float* Wp = W + (size_t)rowT * K;
    const float* Xp = X + (size_t)b * strideX + colT;
    const int cb   = b * HWN + colT;                       // LN stats base
    const int ctxb = (b << 10) + ((colT >> 10) << 8);      // ctx base (pq const per tile)

    // A pre-duplicated as (a,a) packed 64-bit; double-buffered
    __shared__ unsigned long long As2[2][8][128];   // 16 KB
    __shared__ float              Bs [2][8][128];   //  8 KB

    unsigned long long acc[8][4];
#pragma unroll
    for (int i = 0; i < 8; i++)
#pragma unroll
        for (int j = 0; j < 4; j++) acc[i][j] = 0ull;

    const int tid  = threadIdx.x;
    const int tx   = tid & 15, ty = tid >> 4;
    const int aRow = tid >> 1, aK = (tid & 1) << 2;
    const int bK   = tid >> 5, bCol = (tid & 31) << 2;

    const int nT = K >> 3;
    float4 av, bv;

    // prologue: load tile 0 -> buffer 0
    av = *reinterpret_cast<const float4*>(Wp + (size_t)aRow * K + aK);
    {
        int kg = bK;
        bv = *reinterpret_cast<const float4*>(Xp + ((size_t)kg << 12) + bCol);
        bt_xform<BT>(bv, kg, cb, ctxb, lng, lnb, bCol);
    }
    As2[0][aK + 0][aRow] = pack_dup(av.x);
    As2[0][aK + 1][aRow] = pack_dup(av.y);
    As2[0][aK + 2][aRow] = pack_dup(av.z);
    As2[0][aK + 3][aRow] = pack_dup(av.w);
    *reinterpret_cast<float4*>(&Bs[0][bK][bCol]) = bv;
    __syncthreads();

    for (int t = 0; t < nT; t++) {
        const int cur = t & 1;
        const bool more = (t + 1 < nT);
        if (more) {
            int kt = (t + 1) << 3;
            av = *reinterpret_cast<const float4*>(Wp + (size_t)aRow * K + kt + aK);
            int kg = kt + bK;
            bv = *reinterpret_cast<const float4*>(Xp + ((size_t)kg << 12) + bCol);
            bt_xform<BT>(bv, kg, cb, ctxb, lng, lnb, bCol);
        }
#pragma unroll
        for (int kk = 0; kk < 8; kk++) {
            const ulonglong2* ap =
                reinterpret_cast<const ulonglong2*>(&As2[cur][kk][ty * 8]);
            ulonglong2 a01 = ap[0], a23 = ap[1], a45 = ap[2], a67 = ap[3];
            const ulonglong2* bp =
                reinterpret_cast<const ulonglong2*>(&Bs[cur][kk][tx * 8]);
            ulonglong2 b01 = bp[0], b23 = bp[1];
            unsigned long long ar[8] = {a01.x, a01.y, a23.x, a23.y,
                                        a45.x, a45.y, a67.x, a67.y};
            unsigned long long br[4] = {b01.x, b01.y, b23.x, b23.y};
#pragma unroll
            for (int i = 0; i < 8; i++)
#pragma unroll
                for (int j = 0; j < 4; j++) FFMA2(acc[i][j], ar[i], br[j]);
        }
        if (more) {
            const int nxt = cur ^ 1;
            As2[nxt][aK + 0][aRow] = pack_dup(av.x);
            As2[nxt][aK + 1][aRow] = pack_dup(av.y);
            As2[nxt][aK + 2][aRow] = pack_dup(av.z);
            As2[nxt][aK + 3][aRow] = pack_dup(av.w);
            *reinterpret_cast<float4*>(&Bs[nxt][bK][bCol]) = bv;
            __syncthreads();
        }
    }

#pragma unroll
    for (int i = 0; i < 8; i++) {
        int m = rowT + ty * 8 + i;
        float bi = 0.f, rs_ = 0.f, rb_ = 0.f;
        if (EP == EP_PERM_OUT) { rs_ = g_s2[m]; rb_ = g_b2[m]; }
        else bi = bias[m];
#pragma unroll
        for (int j = 0; j < 4; j++) {
            union { unsigned long long u; float2 f; } cv;
            cv.u = acc[i][j];
            float vals[2] = { cv.f.x, cv.f.y };
#pragma unroll
            for (int h2 = 0; h2 < 2; h2++) {
                int col = colT + tx * 8 + j * 2 + h2;
                float v = vals[h2];
                if (EP == EP_PERM_OUT) v = v * rs_ + rb_;
                else v += bi;
                if (EP == EP_LEAKY) v = (v > 0.f) ? v : 0.1f * v;
                if (EP == EP_PERM_P) {
                    // spatial col -> patch col
                    int h = col >> 6, w = col & 63;
                    int pc = ((((h & 1) << 1) | (w & 1)) << 10) | ((h >> 1) << 5) | (w >> 1);
                    Y[((size_t)b * M + m) * HWN + pc] = v;
                } else if (EP == EP_PERM_OUT) {
                    // patch col -> spatial
                    int pq = col >> 10, n = col & 1023;
                    int h = ((n >> 5) << 1) | (pq >> 1);
                    int w = ((n & 31) << 1) | (pq & 1);
                    Y[((size_t)b * M + m) * HWN + h * 64 + w] = v;
                } else {
                    size_t yb = ((size_t)b * M + m) * HWN + col;
                    if (EP == EP_RESID) Y[yb] += v;
                    else Y[yb] = v;
                }
            }
        }
    }
}

// ---------------- host ----------------
extern "C" void kernel_launch(void* const* d_in, const int* in_sizes, int n_in,
                              void* d_out, int out_size)
{
    const float* x     = (const float*)d_in[0];
    const float* dw_w  = (const float*)d_in[1];
    const float* bn1_g = (const float*)d_in[2];
    const float* bn1_b = (const float*)d_in[3];
    const float* bn1_m = (const float*)d_in[4];
    const float* bn1_v = (const float*)d_in[5];
    const float* c1_w  = (const float*)d_in[6];
    const float* c1_b  = (const float*)d_in[7];
    const float* ln1_g = (const float*)d_in[8];
    const float* ln1_b = (const float*)d_in[9];
    const float* qkv_w = (const float*)d_in[10];
    const float* qkv_b = (const float*)d_in[11];
    const float* out_w = (const float*)d_in[12];
    const float* out_b = (const float*)d_in[13];
    const float* ln2_g = (const float*)d_in[14];
    const float* ln2_b = (const float*)d_in[15];
    const float* f1_w  = (const float*)d_in[16];
    const float* f1_b  = (const float*)d_in[17];
    const float* f2_w  = (const float*)d_in[18];
    const float* f2_b  = (const float*)d_in[19];
    const float* lnf_g = (const float*)d_in[20];
    const float* lnf_b = (const float*)d_in[21];
    const float* projw = (const float*)d_in[22];
    const float* bn2_g = (const float*)d_in[23];
    const float* bn2_b = (const float*)d_in[24];
    const float* bn2_m = (const float*)d_in[25];
    const float* bn2_v = (const float*)d_in[26];
    float* out = (float*)d_out;

    void *vp;
    cudaGetSymbolAddress(&vp, g_y);  float* yb = (float*)vp;
    cudaGetSymbolAddress(&vp, g_p);  float* p  = (float*)vp;
    cudaGetSymbolAddress(&vp, g_kv); float* kv = (float*)vp;
    cudaGetSymbolAddress(&vp, g_h);  float* hb = (float*)vp;

    prep_k<<<1, 128>>>(bn2_g, bn2_b, bn2_m, bn2_v);
    dwconv_k<<<dim3(16, CC, BB), 256>>>(x, dw_w, bn1_g, bn1_b, bn1_m, bn1_v);

    // c1: 128->256, spatial cols, patchify-permuted store into p
    gemm_k<BT_NONE, EP_PERM_P><<<dim3(32, 2, BB), 256>>>(
        c1_w, yb, p, c1_b, nullptr, nullptr, DD, CC, (long)CC * HWN);

    for (int l = 0; l < 2; l++) {
        const float* l1g = ln1_g + l * DD;
        const float* l1b = ln1_b + l * DD;
        const float* qw  = qkv_w + (size_t)l * 513 * DD;
        const float* qbi = qkv_b + l * 513;

        colstats_k<<<dim3(128, BB), dim3(32, 8)>>>(p);

        // kv = W_kv @ LN1(p)   (rows 1..512 of qkv)
        gemm_k<BT_LN, EP_STORE><<<dim3(32, 4, BB), 256>>>(
            qw + DD, p, kv, qbi + 1, l1g, l1b, 512, DD, (long)DD * HWN);

        // q + softmax + ctx
        qsoftctx_k<<<128, 256>>>(p, l1g, l1b, qw, qbi);

        // attn = out_w @ (relu(v)*ctx) + out_b ; p += attn   (v rows = kv+256*4096)
        gemm_k<BT_RELUCTX, EP_RESID><<<dim3(32, 2, BB), 256>>>(
            out_w + (size_t)l * DD * DD, kv + (size_t)DD * HWN, p,
            out_b + l * DD, nullptr, nullptr, DD, DD, (long)512 * HWN);

        colstats_k<<<dim3(128, BB), dim3(32, 8)>>>(p);

        // h = leaky(f1 @ LN2(p) + b1)
        gemm_k<BT_LN, EP_LEAKY><<<dim3(32, 4, BB), 256>>>(
            f1_w + (size_t)l * FF_ * DD, p, hb, f1_b + l * FF_,
            ln2_g + l * DD, ln2_b + l * DD, FF_, DD, (long)DD * HWN);

        // p += f2 @ h + b2
        gemm_k<BT_NONE, EP_RESID><<<dim3(32, 2, BB), 256>>>(
            f2_w + (size_t)l * DD * FF_, hb, p, f2_b + l * DD,
            nullptr, nullptr, DD, FF_, (long)FF_ * HWN);
    }

    colstats_k<<<dim3(128, BB), dim3(32, 8)>>>(p);

    // out = BN2(proj @ LNf(p)), un-patchified spatial store
    gemm_k<BT_LN, EP_PERM_OUT><<<dim3(32, 1, BB), 256>>>(
        projw, p, out, nullptr, lnf_g, lnf_b, CC, DD, (long)DD * HWN);
}

// round 4
// speedup vs baseline: 1.9594x; 1.9594x over previous
#include <cuda_runtime.h>
#include <cuda_bf16.h>
#include <cstdint>

// ---------------- problem constants ----------------
#define BB   32
#define CC   128
#define HH   64
#define WW   64
#define DD   256
#define FF_  512
#define HWN  4096          // H*W = 4096 = patch cols per batch too
#define EPS  1e-5f

// ---------------- static scratch ----------------
__device__ float g_y [ (size_t)BB * CC  * HWN ];   // 64 MB  dwconv out
__device__ float g_p [ (size_t)BB * DD  * HWN ];   // 128 MB token tensor
__device__ float g_kv[ (size_t)BB * 512 * HWN ];   // 256 MB k(0..255) v(256..511)
__device__ float g_h [ (size_t)BB * 512 * HWN ];   // 256 MB ffn hidden
__device__ float g_mean[ BB * HWN ];
__device__ float g_rstd[ BB * HWN ];
__device__ float g_ctx [ BB * 4 * DD ];
__device__ float g_s2[CC], g_b2[CC];

// split-bf16 weights (hi/lo), concatenated per-tensor
#define WTOT 983040
__device__ __nv_bfloat16 g_whi[WTOT];
__device__ __nv_bfloat16 g_wlo[WTOT];

// weight offsets (elements)
#define OFF_C1    0
#define LSTRIDE   458752
#define OFF_KV(l)  (32768 + (l) * LSTRIDE)
#define OFF_OUT(l) (OFF_KV(l) + 131072)
#define OFF_F1(l)  (OFF_KV(l) + 196608)
#define OFF_F2(l)  (OFF_KV(l) + 327680)
#define OFF_PROJ  (32768 + 2 * LSTRIDE)

// ---------------- prep: fold BN2 ----------------
__global__ void prep_k(const float* __restrict__ g, const float* __restrict__ b,
                       const float* __restrict__ m, const float* __restrict__ v)
{
    int i = threadIdx.x;
    if (i < CC) {
        float s = g[i] * rsqrtf(v[i] + EPS);
        g_s2[i] = s;
        g_b2[i] = b[i] - m[i] * s;
    }
}

// ---------------- prep: split weights into bf16 hi/lo ----------------
__global__ void wsplit_k(const float* __restrict__ src, int n, int off)
{
    int i = blockIdx.x * 256 + threadIdx.x;
    if (i < n) {
        float v = src[i];
        __nv_bfloat16 h = __float2bfloat16_rn(v);
        g_whi[off + i] = h;
        g_wlo[off + i] = __float2bfloat16_rn(v - __bfloat162float(h));
    }
}

// ---------------- dwconv3x3 + BN1 + leaky ----------------
__global__ void __launch_bounds__(256) dwconv_k(
    const float* __restrict__ x, const float* __restrict__ w,
    const float* __restrict__ bg, const float* __restrict__ bbias,
    const float* __restrict__ bm, const float* __restrict__ bv)
{
    int b = blockIdx.z, c = blockIdx.y;
    int idx = blockIdx.x * 256 + threadIdx.x;
    __shared__ float ws[9];
    __shared__ float sc, sh;
    if (threadIdx.x < 9) ws[threadIdx.x] = w[c * 9 + threadIdx.x];
    if (threadIdx.x == 0) {
        float s = bg[c] * rsqrtf(bv[c] + EPS);
        sc = s; sh = bbias[c] - bm[c] * s;
    }
    __syncthreads();
    int h = idx >> 6, wq = idx & 63;
    const float* xp = x + ((size_t)b * CC + c) * HWN;
    float acc = 0.f;
#pragma unroll
    for (int dh = 0; dh < 3; dh++) {
        int hh = h + dh - 1;
        if (hh < 0 || hh >= HH) continue;
#pragma unroll
        for (int dw = 0; dw < 3; dw++) {
            int ww2 = wq + dw - 1;
            if (ww2 < 0 || ww2 >= WW) continue;
            acc = fmaf(xp[hh * 64 + ww2], ws[dh * 3 + dw], acc);
        }
    }
    float o = acc * sc + sh;
    o = (o > 0.f) ? o : 0.1f * o;
    g_y[((size_t)b * CC + c) * HWN + idx] = o;
}

// ---------------- per-column mean / rstd over D=256 ----------------
__global__ void colstats_k(const float* __restrict__ p)
{
    int b   = blockIdx.y;
    int col = blockIdx.x * 32 + threadIdx.x;
    int ty  = threadIdx.y;
    size_t base = (size_t)b * DD * HWN + col;
    float s = 0.f, s2 = 0.f;
    for (int d = ty; d < DD; d += 8) {
        float v = p[base + ((size_t)d << 12)];
        s += v; s2 = fmaf(v, v, s2);
    }
    __shared__ float sh1[8][32], sh2[8][32];
    sh1[ty][threadIdx.x] = s; sh2[ty][threadIdx.x] = s2;
    __syncthreads();
    if (ty == 0) {
        float a = 0.f, a2 = 0.f;
#pragma unroll
        for (int k = 0; k < 8; k++) { a += sh1[k][threadIdx.x]; a2 += sh2[k][threadIdx.x]; }
        float mean = a * (1.f / DD);
        float var  = a2 * (1.f / DD) - mean * mean;
        g_mean[b * HWN + col] = mean;
        g_rstd[b * HWN + col] = rsqrtf(var + EPS);
    }
}

// ---------------- fused q-GEMV + softmax + ctx ----------------
__global__ void __launch_bounds__(256) qsoftctx_k(
    const float* __restrict__ p,
    const float* __restrict__ lng, const float* __restrict__ lnb,
    const float* __restrict__ wq,  const float* __restrict__ qb)
{
    __shared__ float sprob[1024];
    __shared__ float wqs[256], gs[256], bs[256];
    __shared__ float red[256];
    int tid = threadIdx.x;
    int b = blockIdx.x >> 2, pq = blockIdx.x & 3;
    wqs[tid] = wq[tid]; gs[tid] = lng[tid]; bs[tid] = lnb[tid];
    __syncthreads();
    size_t pbase = (size_t)b * DD * HWN + pq * 1024;
    int cb = b * HWN + pq * 1024;
    float q0 = qb[0];
    float qv[4];
#pragma unroll
    for (int r = 0; r < 4; r++) {
        int n = tid + (r << 8);
        float m_ = g_mean[cb + n], rs_ = g_rstd[cb + n];
        float acc = q0;
#pragma unroll 4
        for (int k = 0; k < 256; k++) {
            float z = (p[pbase + ((size_t)k << 12) + n] - m_) * rs_ * gs[k] + bs[k];
            acc = fmaf(wqs[k], z, acc);
        }
        qv[r] = acc;
    }
    float lm = fmaxf(fmaxf(qv[0], qv[1]), fmaxf(qv[2], qv[3]));
    red[tid] = lm; __syncthreads();
    for (int s = 128; s > 0; s >>= 1) { if (tid < s) red[tid] = fmaxf(red[tid], red[tid + s]); __syncthreads(); }
    float gm = red[0]; __syncthreads();
    float e[4]; float ls = 0.f;
#pragma unroll
    for (int r = 0; r < 4; r++) { e[r] = __expf(qv[r] - gm); ls += e[r]; }
    red[tid] = ls; __syncthreads();
    for (int s = 128; s > 0; s >>= 1) { if (tid < s) red[tid] += red[tid + s]; __syncthreads(); }
    float inv = 1.f / red[0];
#pragma unroll
    for (int r = 0; r < 4; r++) sprob[tid + (r << 8)] = e[r] * inv;
    __syncthreads();
    int warp = tid >> 5, lane = tid & 31;
    for (int d = warp; d < 256; d += 8) {
        const float* kr = g_kv + ((size_t)b * 512 + d) * HWN + pq * 1024;
        float acc = 0.f;
#pragma unroll 8
        for (int n = lane; n < 1024; n += 32) acc = fmaf(kr[n], sprob[n], acc);
#pragma unroll
        for (int o = 16; o > 0; o >>= 1) acc += __shfl_down_sync(0xffffffffu, acc, o);
        if (lane == 0) g_ctx[(b << 10) + (pq << 8) + d] = acc;
    }
}

// ---------------- tensor-core GEMM (bf16 split, m16n8k16) ----------------
enum { BT_NONE = 0, BT_LN = 1, BT_RELUCTX = 2 };
enum { EP_STORE = 0, EP_LEAKY = 1, EP_RESID = 2, EP_PERM_P = 3, EP_PERM_OUT = 4 };

template<int BT>
__device__ __forceinline__ void bt_xform(float4& bv, int kg, int cb, int ctxb,
                                         const float* __restrict__ lng,
                                         const float* __restrict__ lnb,
                                         int bCol)
{
    if (BT == BT_LN) {
        float gk = lng[kg], bk = lnb[kg];
        int c = cb + bCol;
        bv.x = (bv.x - g_mean[c + 0]) * g_rstd[c + 0] * gk + bk;
        bv.y = (bv.y - g_mean[c + 1]) * g_rstd[c + 1] * gk + bk;
        bv.z = (bv.z - g_mean[c + 2]) * g_rstd[c + 2] * gk + bk;
        bv.w = (bv.w - g_mean[c + 3]) * g_rstd[c + 3] * gk + bk;
    } else if (BT == BT_RELUCTX) {
        float cv = g_ctx[ctxb + kg];
        bv.x = fmaxf(bv.x, 0.f) * cv; bv.y = fmaxf(bv.y, 0.f) * cv;
        bv.z = fmaxf(bv.z, 0.f) * cv; bv.w = fmaxf(bv.w, 0.f) * cv;
    }
}

__device__ __forceinline__ void split2(float a, float b, uint32_t& hi, uint32_t& lo)
{
    __nv_bfloat16 ha = __float2bfloat16_rn(a), hb = __float2bfloat16_rn(b);
    float ra = a - __bfloat162float(ha);
    float rb = b - __bfloat162float(hb);
    __nv_bfloat16 la = __float2bfloat16_rn(ra), lb = __float2bfloat16_rn(rb);
    hi = (uint32_t)__bfloat16_as_ushort(ha) | ((uint32_t)__bfloat16_as_ushort(hb) << 16);
    lo = (uint32_t)__bfloat16_as_ushort(la) | ((uint32_t)__bfloat16_as_ushort(lb) << 16);
}

#define MMA_BF16(D, A0, A1, A2, A3, B0, B1)                                   \
    asm volatile("mma.sync.aligned.m16n8k16.row.col.f32.bf16.bf16.f32 "       \
        "{%0,%1,%2,%3},{%4,%5,%6,%7},{%8,%9},{%0,%1,%2,%3};"                  \
        : "+f"((D)[0]), "+f"((D)[1]), "+f"((D)[2]), "+f"((D)[3])              \
        : "r"(A0), "r"(A1), "r"(A2), "r"(A3), "r"(B0), "r"(B1))

// smem buffer layout (bytes): Ahi 10240 | Alo 10240 | Bhi 8704 | Blo 8704
#define SBUF     37888
#define SOFF_ALO 10240
#define SOFF_BHI 20480
#define SOFF_BLO 29184
#define SMEM_DYN (2 * SBUF)

template<int BT, int EP>
__global__ void gemm_tc(int woff, const float* __restrict__ X, float* __restrict__ Y,
                        const float* __restrict__ bias,
                        const float* __restrict__ lng, const float* __restrict__ lnb,
                        int M, int K, long strideX)
{
    extern __shared__ uint8_t smem_raw[];

    const int b    = blockIdx.z;
    const int colT = blockIdx.x * 128;
    const int rowT = blockIdx.y * 128;
    const float* Xp = X + (size_t)b * strideX + colT;
    const int cb   = b * HWN + colT;
    const int ctxb = (b << 10) + ((colT >> 10) << 8);

    const int tid  = threadIdx.x;
    const int wid  = tid >> 5;
    const int lane = tid & 31;
    const int gid  = lane >> 2;       // 0..7
    const int tig  = lane & 3;        // 0..3
    const int mw   = (wid & 1) * 64;  // warp m offset
    const int nw   = (wid >> 1) * 32; // warp n offset

    // producer indices
    const int ar = tid >> 1, asg = tid & 1;        // A: row, 32B segment
    const int bn0 = (tid & 31) * 4;                // B: col group

    float acc[4][4][4];
#pragma unroll
    for (int i = 0; i < 4; i++)
#pragma unroll
        for (int j = 0; j < 4; j++)
#pragma unroll
            for (int k = 0; k < 4; k++) acc[i][j][k] = 0.f;

    const int nT = K >> 5;   // kTile = 32

    uint4 aH[2], aL[2];
    float4 v0[2], v1[2];

    // ---- fetch tile (global -> regs) ----
    auto fetch = [&](int k0) {
        const uint4* sh = reinterpret_cast<const uint4*>(
            g_whi + woff + (size_t)(rowT + ar) * K + k0) + 2 * asg;
        const uint4* sl = reinterpret_cast<const uint4*>(
            g_wlo + woff + (size_t)(rowT + ar) * K + k0) + 2 * asg;
        aH[0] = sh[0]; aH[1] = sh[1];
        aL[0] = sl[0]; aL[1] = sl[1];
#pragma unroll
        for (int i = 0; i < 2; i++) {
            int k2g = (tid >> 5) + 8 * i;
            int kk  = k0 + 2 * k2g;
            v0[i] = reinterpret_cast<const float4*>(Xp + ((size_t)kk << 12))[tid & 31];
            v1[i] = reinterpret_cast<const float4*>(Xp + ((size_t)(kk + 1) << 12))[tid & 31];
            bt_xform<BT>(v0[i], kk,     cb, ctxb, lng, lnb, bn0);
            bt_xform<BT>(v1[i], kk + 1, cb, ctxb, lng, lnb, bn0);
        }
    };

    // ---- store tile (regs -> smem buf) ----
    auto store = [&](int buf) {
        uint8_t* base = smem_raw + buf * SBUF;
        __nv_bfloat16* pAhi = reinterpret_cast<__nv_bfloat16*>(base);
        __nv_bfloat16* pAlo = reinterpret_cast<__nv_bfloat16*>(base + SOFF_ALO);
        uint32_t* pBhi = reinterpret_cast<uint32_t*>(base + SOFF_BHI);
        uint32_t* pBlo = reinterpret_cast<uint32_t*>(base + SOFF_BLO);

        uint4* dh = reinterpret_cast<uint4*>(pAhi + ar * 40 + 16 * asg);
        dh[0] = aH[0]; dh[1] = aH[1];
        uint4* dl = reinterpret_cast<uint4*>(pAlo + ar * 40 + 16 * asg);
        dl[0] = aL[0]; dl[1] = aL[1];

#pragma unroll
        for (int i = 0; i < 2; i++) {
            int k2g = (tid >> 5) + 8 * i;
            uint32_t hw[4], lw[4];
            split2(v0[i].x, v1[i].x, hw[0], lw[0]);
            split2(v0[i].y, v1[i].y, hw[1], lw[1]);
            split2(v0[i].z, v1[i].z, hw[2], lw[2]);
            split2(v0[i].w, v1[i].w, hw[3], lw[3]);
            *reinterpret_cast<uint4*>(&pBhi[k2g * 136 + bn0]) =
                make_uint4(hw[0], hw[1], hw[2], hw[3]);
            *reinterpret_cast<uint4*>(&pBlo[k2g * 136 + bn0]) =
                make_uint4(lw[0], lw[1], lw[2], lw[3]);
        }
    };

    // ---- compute one kTile from smem buf ----
    auto compute = [&](int buf) {
        uint8_t* base = smem_raw + buf * SBUF;
        const __nv_bfloat16* pAhi = reinterpret_cast<const __nv_bfloat16*>(base);
        const __nv_bfloat16* pAlo = reinterpret_cast<const __nv_bfloat16*>(base + SOFF_ALO);
        const uint32_t* pBhi = reinterpret_cast<const uint32_t*>(base + SOFF_BHI);
        const uint32_t* pBlo = reinterpret_cast<const uint32_t*>(base + SOFF_BLO);

#pragma unroll
        for (int ks = 0; ks < 2; ks++) {
            uint32_t bh[4][2], bl[4][2];
#pragma unroll
            for (int ni = 0; ni < 4; ni++) {
                int wi = (tig + 8 * ks) * 136 + nw + 8 * ni + gid;
                bh[ni][0] = pBhi[wi]; bh[ni][1] = pBhi[wi + 544];
                bl[ni][0] = pBlo[wi]; bl[ni][1] = pBlo[wi + 544];
            }
#pragma unroll
            for (int mi = 0; mi < 4; mi++) {
                int o = (mw + 16 * mi + gid) * 40 + 16 * ks + 2 * tig;
                uint32_t ah0 = *reinterpret_cast<const uint32_t*>(pAhi + o);
                uint32_t ah1 = *reinterpret_cast<const uint32_t*>(pAhi + o + 320);
                uint32_t ah2 = *reinterpret_cast<const uint32_t*>(pAhi + o + 8);
                uint32_t ah3 = *reinterpret_cast<const uint32_t*>(pAhi + o + 328);
                uint32_t al0 = *reinterpret_cast<const uint32_t*>(pAlo + o);
                uint32_t al1 = *reinterpret_cast<const uint32_t*>(pAlo + o + 320);
                uint32_t al2 = *reinterpret_cast<const uint32_t*>(pAlo + o + 8);
                uint32_t al3 = *reinterpret_cast<const uint32_t*>(pAlo + o + 328);
#pragma unroll
                for (int ni = 0; ni < 4; ni++) {
                    MMA_BF16(acc[mi][ni], ah0, ah1, ah2, ah3, bh[ni][0], bh[ni][1]);
                    MMA_BF16(acc[mi][ni], ah0, ah1, ah2, ah3, bl[ni][0], bl[ni][1]);
                    MMA_BF16(acc[mi][ni], al0, al1, al2, al3, bh[ni][0], bh[ni][1]);
                }
            }
        }
    };

    // ---- pipeline ----
    fetch(0);
    store(0);
    __syncthreads();
    for (int t = 0; t < nT; t++) {
        const int cur = t & 1;
        const bool more = (t + 1 < nT);
        if (more) fetch((t + 1) << 5);
        compute(cur);
        if (more) {
            store(cur ^ 1);
            __syncthreads();
        }
    }

    // ---- epilogue ----
#pragma unroll
    for (int mi = 0; mi < 4; mi++) {
        int m0 = rowT + mw + 16 * mi + gid;
        float bi0, bi1, rs0 = 0.f, rb0 = 0.f, rs1 = 0.f, rb1 = 0.f;
        if (EP == EP_PERM_OUT) {
            rs0 = g_s2[m0]; rb0 = g_b2[m0];
            rs1 = g_s2[m0 + 8]; rb1 = g_b2[m0 + 8];
            bi0 = bi1 = 0.f;
        } else { bi0 = bias[m0]; bi1 = bias[m0 + 8]; }
#pragma unroll
        for (int ni = 0; ni < 4; ni++) {
            int c0 = colT + nw + 8 * ni + 2 * tig;
            float e0 = acc[mi][ni][0], e1 = acc[mi][ni][1];
            float e2 = acc[mi][ni][2], e3 = acc[mi][ni][3];
            if (EP == EP_PERM_OUT) {
                e0 = e0 * rs0 + rb0; e1 = e1 * rs0 + rb0;
                e2 = e2 * rs1 + rb1; e3 = e3 * rs1 + rb1;
            } else {
                e0 += bi0; e1 += bi0; e2 += bi1; e3 += bi1;
            }
            if (EP == EP_LEAKY) {
                e0 = (e0 > 0.f) ? e0 : 0.1f * e0; e1 = (e1 > 0.f) ? e1 : 0.1f * e1;
                e2 = (e2 > 0.f) ? e2 : 0.1f * e2; e3 = (e3 > 0.f) ? e3 : 0.1f * e3;
            }
            if (EP == EP_PERM_P) {
                float vv[4] = {e0, e1, e2, e3};
#pragma unroll
                for (int q = 0; q < 4; q++) {
                    int m = m0 + (q >> 1) * 8;
                    int col = c0 + (q & 1);
                    int h = col >> 6, w = col & 63;
                    int pc = ((((h & 1) << 1) | (w & 1)) << 10) | ((h >> 1) << 5) | (w >> 1);
                    Y[((size_t)b * M + m) * HWN + pc] = vv[q];
                }
            } else if (EP == EP_PERM_OUT) {
                float vv[4] = {e0, e1, e2, e3};
#pragma unroll
                for (int q = 0; q < 4; q++) {
                    int m = m0 + (q >> 1) * 8;
                    int col = c0 + (q & 1);
                    int pq = col >> 10, n = col & 1023;
                    int h = ((n >> 5) << 1) | (pq >> 1);
                    int w = ((n & 31) << 1) | (pq & 1);
                    Y[((size_t)b * M + m) * HWN + h * 64 + w] = vv[q];
                }
            } else {
                float2* y0 = reinterpret_cast<float2*>(&Y[((size_t)b * M + m0) * HWN + c0]);
                float2* y1 = reinterpret_cast<float2*>(&Y[((size_t)b * M + m0 + 8) * HWN + c0]);
                if (EP == EP_RESID) {
                    float2 o0 = *y0, o1 = *y1;
                    o0.x += e0; o0.y += e1; o1.x += e2; o1.y += e3;
                    *y0 = o0; *y1 = o1;
                } else {
                    *y0 = make_float2(e0, e1);
                    *y1 = make_float2(e2, e3);
                }
            }
        }
    }
}

// ---------------- host ----------------
template<int BT, int EP>
static void launch_gemm(int woff, const float* X, float* Y, const float* bias,
                        const float* lng, const float* lnb,
                        int M, int K, long strideX)
{
    cudaFuncSetAttribute(gemm_tc<BT, EP>,
                         cudaFuncAttributeMaxDynamicSharedMemorySize, SMEM_DYN);
    gemm_tc<BT, EP><<<dim3(32, M / 128, BB), 256, SMEM_DYN>>>(
        woff, X, Y, bias, lng, lnb, M, K, strideX);
}

extern "C" void kernel_launch(void* const* d_in, const int* in_sizes, int n_in,
                              void* d_out, int out_size)
{
    const float* x     = (const float*)d_in[0];
    const float* dw_w  = (const float*)d_in[1];
    const float* bn1_g = (const float*)d_in[2];
    const float* bn1_b = (const float*)d_in[3];
    const float* bn1_m = (const float*)d_in[4];
    const float* bn1_v = (const float*)d_in[5];
    const float* c1_w  = (const float*)d_in[6];
    const float* c1_b  = (const float*)d_in[7];
    const float* ln1_g = (const float*)d_in[8];
    const float* ln1_b = (const float*)d_in[9];
    const float* qkv_w = (const float*)d_in[10];
    const float* qkv_b = (const float*)d_in[11];
    const float* out_w = (const float*)d_in[12];
    const float* out_b = (const float*)d_in[13];
    const float* ln2_g = (const float*)d_in[14];
    const float* ln2_b = (const float*)d_in[15];
    const float* f1_w  = (const float*)d_in[16];
    const float* f1_b  = (const float*)d_in[17];
    const float* f2_w  = (const float*)d_in[18];
    const float* f2_b  = (const float*)d_in[19];
    const float* lnf_g = (const float*)d_in[20];
    const float* lnf_b = (const float*)d_in[21];
    const float* projw = (const float*)d_in[22];
    const float* bn2_g = (const float*)d_in[23];
    const float* bn2_b = (const float*)d_in[24];
    const float* bn2_m = (const float*)d_in[25];
    const float* bn2_v = (const float*)d_in[26];
    float* out = (float*)d_out;

    void *vp;
    cudaGetSymbolAddress(&vp, g_y);  float* yb = (float*)vp;
    cudaGetSymbolAddress(&vp, g_p);  float* p  = (float*)vp;
    cudaGetSymbolAddress(&vp, g_kv); float* kv = (float*)vp;
    cudaGetSymbolAddress(&vp, g_h);  float* hb = (float*)vp;

    prep_k<<<1, 128>>>(bn2_g, bn2_b, bn2_m, bn2_v);

    // split all weights into bf16 hi/lo
    wsplit_k<<<(32768 + 255) / 256, 256>>>(c1_w, 32768, OFF_C1);
    for (int l = 0; l < 2; l++) {
        const float* qw = qkv_w + (size_t)l * 513 * DD;
        wsplit_k<<<(131072 + 255) / 256, 256>>>(qw + DD, 131072, OFF_KV(l));
        wsplit_k<<<(65536  + 255) / 256, 256>>>(out_w + (size_t)l * DD * DD, 65536, OFF_OUT(l));
        wsplit_k<<<(131072 + 255) / 256, 256>>>(f1_w + (size_t)l * FF_ * DD, 131072, OFF_F1(l));
        wsplit_k<<<(131072 + 255) / 256, 256>>>(f2_w + (size_t)l * DD * FF_, 131072, OFF_F2(l));
    }
    wsplit_k<<<(32768 + 255) / 256, 256>>>(projw, 32768, OFF_PROJ);

    dwconv_k<<<dim3(16, CC, BB), 256>>>(x, dw_w, bn1_g, bn1_b, bn1_m, bn1_v);

    // c1: 128->256, spatial cols, patchify-permuted store into p
    launch_gemm<BT_NONE, EP_PERM_P>(OFF_C1, yb, p, c1_b, nullptr, nullptr,
                                    DD, CC, (long)CC * HWN);

    for (int l = 0; l < 2; l++) {
        const float* l1g = ln1_g + l * DD;
        const float* l1b = ln1_b + l * DD;
        const float* qw  = qkv_w + (size_t)l * 513 * DD;
        const float* qbi = qkv_b + l * 513;

        colstats_k<<<dim3(128, BB), dim3(32, 8)>>>(p);

        // kv = W_kv @ LN1(p)
        launch_gemm<BT_LN, EP_STORE>(OFF_KV(l), p, kv, qbi + 1, l1g, l1b,
                                     512, DD, (long)DD * HWN);

        // q + softmax + ctx
        qsoftctx_k<<<128, 256>>>(p, l1g, l1b, qw, qbi);

        // attn = out_w @ (relu(v)*ctx) + out_b ; p += attn
        launch_gemm<BT_RELUCTX, EP_RESID>(OFF_OUT(l), kv + (size_t)DD * HWN, p,
                                          out_b + l * DD, nullptr, nullptr,
                                          DD, DD, (long)512 * HWN);

        colstats_k<<<dim3(128, BB), dim3(32, 8)>>>(p);

        // h = leaky(f1 @ LN2(p) + b1)
        launch_gemm<BT_LN, EP_LEAKY>(OFF_F1(l), p, hb, f1_b + l * FF_,
                                     ln2_g + l * DD, ln2_b + l * DD,
                                     FF_, DD, (long)DD * HWN);

        // p += f2 @ h + b2
        launch_gemm<BT_NONE, EP_RESID>(OFF_F2(l), hb, p, f2_b + l * DD,
                                       nullptr, nullptr, DD, FF_, (long)FF_ * HWN);
    }

    colstats_k<<<dim3(128, BB), dim3(32, 8)>>>(p);

    // out = BN2(proj @ LNf(p)), un-patchified spatial store
    launch_gemm<BT_LN, EP_PERM_OUT>(OFF_PROJ, p, out, nullptr, lnf_g, lnf_b,
                                    CC, DD, (long)DD * HWN);
}

// round 5
// speedup vs baseline: 1.9628x; 1.0017x over previous
#include <cuda_runtime.h>
#include <cuda_bf16.h>
#include <cstdint>

// ---------------- problem constants ----------------
#define BB   32
#define CC   128
#define HH   64
#define WW   64
#define DD   256
#define FF_  512
#define HWN  4096
#define EPS  1e-5f

// ---------------- static scratch ----------------
__device__ float g_p [ (size_t)BB * DD  * HWN ];   // 128 MB token tensor (fp32)
__device__ float g_kv[ (size_t)BB * 512 * HWN ];   // 256 MB k(0..255) v(256..511) fp32
__device__ float g_ctx [ BB * 4 * DD ];
__device__ float g_s2[CC], g_b2[CC];

// pre-split bf16 activations (hi/lo), row-major [b][row][4096]
__device__ __nv_bfloat16 g_zhi[(size_t)BB * DD  * HWN];   // 64 MB  LN output
__device__ __nv_bfloat16 g_zlo[(size_t)BB * DD  * HWN];
__device__ __nv_bfloat16 g_hhi[(size_t)BB * FF_ * HWN];   // 128 MB ffn hidden
__device__ __nv_bfloat16 g_hlo[(size_t)BB * FF_ * HWN];
__device__ __nv_bfloat16 g_yhi[(size_t)BB * CC  * HWN];   // 32 MB  dwconv out
__device__ __nv_bfloat16 g_ylo[(size_t)BB * CC  * HWN];

// split-bf16 weights (hi/lo)
#define WTOT 983040
__device__ __nv_bfloat16 g_whi[WTOT];
__device__ __nv_bfloat16 g_wlo[WTOT];

#define OFF_C1    0
#define LSTRIDE   458752
#define OFF_KV(l)  (32768 + (l) * LSTRIDE)
#define OFF_OUT(l) (OFF_KV(l) + 131072)
#define OFF_F1(l)  (OFF_KV(l) + 196608)
#define OFF_F2(l)  (OFF_KV(l) + 327680)
#define OFF_PROJ  (32768 + 2 * LSTRIDE)

// ---------------- prep ----------------
__global__ void prep_k(const float* __restrict__ g, const float* __restrict__ b,
                       const float* __restrict__ m, const float* __restrict__ v)
{
    int i = threadIdx.x;
    if (i < CC) {
        float s = g[i] * rsqrtf(v[i] + EPS);
        g_s2[i] = s;
        g_b2[i] = b[i] - m[i] * s;
    }
}

__global__ void wsplit_k(const float* __restrict__ src, int n, int off)
{
    int i = blockIdx.x * 256 + threadIdx.x;
    if (i < n) {
        float v = src[i];
        __nv_bfloat16 h = __float2bfloat16_rn(v);
        g_whi[off + i] = h;
        g_wlo[off + i] = __float2bfloat16_rn(v - __bfloat162float(h));
    }
}

// ---------------- dwconv3x3 + BN1 + leaky -> bf16 hi/lo ----------------
__global__ void __launch_bounds__(256) dwconv_k(
    const float* __restrict__ x, const float* __restrict__ w,
    const float* __restrict__ bg, const float* __restrict__ bbias,
    const float* __restrict__ bm, const float* __restrict__ bv)
{
    int b = blockIdx.z, c = blockIdx.y;
    int idx = blockIdx.x * 256 + threadIdx.x;
    __shared__ float ws[9];
    __shared__ float sc, sh;
    if (threadIdx.x < 9) ws[threadIdx.x] = w[c * 9 + threadIdx.x];
    if (threadIdx.x == 0) {
        float s = bg[c] * rsqrtf(bv[c] + EPS);
        sc = s; sh = bbias[c] - bm[c] * s;
    }
    __syncthreads();
    int h = idx >> 6, wq = idx & 63;
    const float* xp = x + ((size_t)b * CC + c) * HWN;
    float acc = 0.f;
#pragma unroll
    for (int dh = 0; dh < 3; dh++) {
        int hh = h + dh - 1;
        if (hh < 0 || hh >= HH) continue;
#pragma unroll
        for (int dw = 0; dw < 3; dw++) {
            int ww2 = wq + dw - 1;
            if (ww2 < 0 || ww2 >= WW) continue;
            acc = fmaf(xp[hh * 64 + ww2], ws[dh * 3 + dw], acc);
        }
    }
    float o = acc * sc + sh;
    o = (o > 0.f) ? o : 0.1f * o;
    size_t oidx = ((size_t)b * CC + c) * HWN + idx;
    __nv_bfloat16 hi = __float2bfloat16_rn(o);
    g_yhi[oidx] = hi;
    g_ylo[oidx] = __float2bfloat16_rn(o - __bfloat162float(hi));
}

// ---------------- colstats + LN -> z bf16 hi/lo ----------------
__global__ void __launch_bounds__(256) colstats_z_k(
    const float* __restrict__ p,
    const float* __restrict__ lng, const float* __restrict__ lnb)
{
    int b  = blockIdx.y;
    int tx = threadIdx.x, ty = threadIdx.y;
    int col = blockIdx.x * 32 + tx;
    int lt = ty * 32 + tx;

    __shared__ float sg[256], sb[256];
    sg[lt] = lng[lt]; sb[lt] = lnb[lt];

    size_t base = (size_t)b * DD * HWN + col;
    float vals[32];
    float s = 0.f, s2 = 0.f;
#pragma unroll
    for (int j = 0; j < 32; j++) {
        float v = p[base + ((size_t)(ty * 32 + j) << 12)];
        vals[j] = v; s += v; s2 = fmaf(v, v, s2);
    }
    __shared__ float sh1[8][32], sh2[8][32], smean[32], srstd[32];
    sh1[ty][tx] = s; sh2[ty][tx] = s2;
    __syncthreads();
    if (ty == 0) {
        float a = 0.f, a2 = 0.f;
#pragma unroll
        for (int k = 0; k < 8; k++) { a += sh1[k][tx]; a2 += sh2[k][tx]; }
        float mean = a * (1.f / DD);
        float var  = a2 * (1.f / DD) - mean * mean;
        smean[tx] = mean;
        srstd[tx] = rsqrtf(var + EPS);
    }
    __syncthreads();
    float mean = smean[tx], rstd = srstd[tx];
#pragma unroll
    for (int j = 0; j < 32; j++) {
        int d = ty * 32 + j;
        float z = (vals[j] - mean) * rstd * sg[d] + sb[d];
        __nv_bfloat16 hi = __float2bfloat16_rn(z);
        size_t o = base + ((size_t)d << 12);
        g_zhi[o] = hi;
        g_zlo[o] = __float2bfloat16_rn(z - __bfloat162float(hi));
    }
}

// ---------------- fused q-GEMV + softmax + ctx (reads pre-split z) ---------
__global__ void __launch_bounds__(256) qsoftctx_k(
    const float* __restrict__ wq, const float* __restrict__ qb)
{
    __shared__ float sprob[1024];
    __shared__ float wqs[256];
    __shared__ float red[256];
    int tid = threadIdx.x;
    int b = blockIdx.x >> 2, pq = blockIdx.x & 3;
    wqs[tid] = wq[tid];
    __syncthreads();
    size_t zbase = (size_t)b * DD * HWN + pq * 1024;
    float q0 = qb[0];
    float qv[4];
#pragma unroll
    for (int r = 0; r < 4; r++) {
        int n = tid + (r << 8);
        float acc = q0;
#pragma unroll 4
        for (int k = 0; k < 256; k++) {
            size_t o = zbase + ((size_t)k << 12) + n;
            float z = __bfloat162float(g_zhi[o]) + __bfloat162float(g_zlo[o]);
            acc = fmaf(wqs[k], z, acc);
        }
        qv[r] = acc;
    }
    float lm = fmaxf(fmaxf(qv[0], qv[1]), fmaxf(qv[2], qv[3]));
    red[tid] = lm; __syncthreads();
    for (int s = 128; s > 0; s >>= 1) { if (tid < s) red[tid] = fmaxf(red[tid], red[tid + s]); __syncthreads(); }
    float gm = red[0]; __syncthreads();
    float e[4]; float ls = 0.f;
#pragma unroll
    for (int r = 0; r < 4; r++) { e[r] = __expf(qv[r] - gm); ls += e[r]; }
    red[tid] = ls; __syncthreads();
    for (int s = 128; s > 0; s >>= 1) { if (tid < s) red[tid] += red[tid + s]; __syncthreads(); }
    float inv = 1.f / red[0];
#pragma unroll
    for (int r = 0; r < 4; r++) sprob[tid + (r << 8)] = e[r] * inv;
    __syncthreads();
    int warp = tid >> 5, lane = tid & 31;
    for (int d = warp; d < 256; d += 8) {
        const float* kr = g_kv + ((size_t)b * 512 + d) * HWN + pq * 1024;
        float acc = 0.f;
#pragma unroll 8
        for (int n = lane; n < 1024; n += 32) acc = fmaf(kr[n], sprob[n], acc);
#pragma unroll
        for (int o = 16; o > 0; o >>= 1) acc += __shfl_down_sync(0xffffffffu, acc, o);
        if (lane == 0) g_ctx[(b << 10) + (pq << 8) + d] = acc;
    }
}

// ---------------- tensor-core GEMM ----------------
enum { BT_PRE = 0, BT_V = 1 };
enum { EP_STORE = 0, EP_LEAKY_H = 1, EP_RESID = 2, EP_PERM_P = 3, EP_PERM_OUT = 4 };

__device__ __forceinline__ void split2(float a, float b, uint32_t& hi, uint32_t& lo)
{
    __nv_bfloat16 ha = __float2bfloat16_rn(a), hb = __float2bfloat16_rn(b);
    float ra = a - __bfloat162float(ha);
    float rb = b - __bfloat162float(hb);
    __nv_bfloat16 la = __float2bfloat16_rn(ra), lb = __float2bfloat16_rn(rb);
    hi = (uint32_t)__bfloat16_as_ushort(ha) | ((uint32_t)__bfloat16_as_ushort(hb) << 16);
    lo = (uint32_t)__bfloat16_as_ushort(la) | ((uint32_t)__bfloat16_as_ushort(lb) << 16);
}

#define MMA_BF16(D, A0, A1, A2, A3, B0, B1)                                   \
    asm volatile("mma.sync.aligned.m16n8k16.row.col.f32.bf16.bf16.f32 "       \
        "{%0,%1,%2,%3},{%4,%5,%6,%7},{%8,%9},{%0,%1,%2,%3};"                  \
        : "+f"((D)[0]), "+f"((D)[1]), "+f"((D)[2]), "+f"((D)[3])              \
        : "r"(A0), "r"(A1), "r"(A2), "r"(A3), "r"(B0), "r"(B1))

// smem buffer layout (bytes): Ahi 10240 | Alo 10240 | Bhi 8704 | Blo 8704
#define SBUF     37888
#define SOFF_ALO 10240
#define SOFF_BHI 20480
#define SOFF_BLO 29184
#define SMEM_DYN (2 * SBUF)

template<int BT, int EP>
__global__ void gemm_tc(int woff, const float* __restrict__ Xf,
                        const __nv_bfloat16* __restrict__ Bhg,
                        const __nv_bfloat16* __restrict__ Blg,
                        float* __restrict__ Y, const float* __restrict__ bias,
                        int M, int K, long strideB)
{
    extern __shared__ uint8_t smem_raw[];

    const int b    = blockIdx.z;
    const int colT = blockIdx.x * 128;
    const int rowT = blockIdx.y * 128;
    const float* Xp = (BT == BT_V) ? (Xf + (size_t)b * strideB + colT) : nullptr;
    const __nv_bfloat16* Bhp = (BT == BT_PRE) ? (Bhg + (size_t)b * strideB + colT) : nullptr;
    const __nv_bfloat16* Blp = (BT == BT_PRE) ? (Blg + (size_t)b * strideB + colT) : nullptr;
    const int ctxb = (b << 10) + ((colT >> 10) << 8);

    const int tid  = threadIdx.x;
    const int wid  = tid >> 5;
    const int lane = tid & 31;
    const int gid  = lane >> 2;
    const int tig  = lane & 3;
    const int mw   = (wid & 1) * 64;
    const int nw   = (wid >> 1) * 32;

    const int ar = tid >> 1, asg = tid & 1;
    const int bn0 = (tid & 31) * 4;

    float acc[4][4][4];
#pragma unroll
    for (int i = 0; i < 4; i++)
#pragma unroll
        for (int j = 0; j < 4; j++)
#pragma unroll
            for (int k = 0; k < 4; k++) acc[i][j][k] = 0.f;

    const int nT = K >> 5;

    uint4 aH[2], aL[2];
    float4 v0[2], v1[2];        // BT_V path
    uint4 bQH[2], bQL[2];       // BT_PRE path

    auto fetch = [&](int k0) {
        const uint4* sh = reinterpret_cast<const uint4*>(
            g_whi + woff + (size_t)(rowT + ar) * K + k0) + 2 * asg;
        const uint4* sl = reinterpret_cast<const uint4*>(
            g_wlo + woff + (size_t)(rowT + ar) * K + k0) + 2 * asg;
        aH[0] = sh[0]; aH[1] = sh[1];
        aL[0] = sl[0]; aL[1] = sl[1];
#pragma unroll
        for (int i = 0; i < 2; i++) {
            int k2g = wid + 8 * i;
            int kk  = k0 + 2 * k2g;
            if (BT == BT_PRE) {
                uint2 r0 = *reinterpret_cast<const uint2*>(Bhp + (size_t)kk * HWN + bn0);
                uint2 r1 = *reinterpret_cast<const uint2*>(Bhp + (size_t)(kk + 1) * HWN + bn0);
                bQH[i] = make_uint4(__byte_perm(r0.x, r1.x, 0x5410),
                                    __byte_perm(r0.x, r1.x, 0x7632),
                                    __byte_perm(r0.y, r1.y, 0x5410),
                                    __byte_perm(r0.y, r1.y, 0x7632));
                uint2 s0 = *reinterpret_cast<const uint2*>(Blp + (size_t)kk * HWN + bn0);
                uint2 s1 = *reinterpret_cast<const uint2*>(Blp + (size_t)(kk + 1) * HWN + bn0);
                bQL[i] = make_uint4(__byte_perm(s0.x, s1.x, 0x5410),
                                    __byte_perm(s0.x, s1.x, 0x7632),
                                    __byte_perm(s0.y, s1.y, 0x5410),
                                    __byte_perm(s0.y, s1.y, 0x7632));
            } else {
                v0[i] = reinterpret_cast<const float4*>(Xp + ((size_t)kk << 12))[lane];
                v1[i] = reinterpret_cast<const float4*>(Xp + ((size_t)(kk + 1) << 12))[lane];
                float c0v = g_ctx[ctxb + kk], c1v = g_ctx[ctxb + kk + 1];
                v0[i].x = fmaxf(v0[i].x, 0.f) * c0v; v0[i].y = fmaxf(v0[i].y, 0.f) * c0v;
                v0[i].z = fmaxf(v0[i].z, 0.f) * c0v; v0[i].w = fmaxf(v0[i].w, 0.f) * c0v;
                v1[i].x = fmaxf(v1[i].x, 0.f) * c1v; v1[i].y = fmaxf(v1[i].y, 0.f) * c1v;
                v1[i].z = fmaxf(v1[i].z, 0.f) * c1v; v1[i].w = fmaxf(v1[i].w, 0.f) * c1v;
            }
        }
    };

    auto store = [&](int buf) {
        uint8_t* base = smem_raw + buf * SBUF;
        __nv_bfloat16* pAhi = reinterpret_cast<__nv_bfloat16*>(base);
        __nv_bfloat16* pAlo = reinterpret_cast<__nv_bfloat16*>(base + SOFF_ALO);
        uint32_t* pBhi = reinterpret_cast<uint32_t*>(base + SOFF_BHI);
        uint32_t* pBlo = reinterpret_cast<uint32_t*>(base + SOFF_BLO);

        uint4* dh = reinterpret_cast<uint4*>(pAhi + ar * 40 + 16 * asg);
        dh[0] = aH[0]; dh[1] = aH[1];
        uint4* dl = reinterpret_cast<uint4*>(pAlo + ar * 40 + 16 * asg);
        dl[0] = aL[0]; dl[1] = aL[1];

#pragma unroll
        for (int i = 0; i < 2; i++) {
            int k2g = wid + 8 * i;
            if (BT == BT_PRE) {
                *reinterpret_cast<uint4*>(&pBhi[k2g * 136 + bn0]) = bQH[i];
                *reinterpret_cast<uint4*>(&pBlo[k2g * 136 + bn0]) = bQL[i];
            } else {
                uint32_t hw[4], lw[4];
                split2(v0[i].x, v1[i].x, hw[0], lw[0]);
                split2(v0[i].y, v1[i].y, hw[1], lw[1]);
                split2(v0[i].z, v1[i].z, hw[2], lw[2]);
                split2(v0[i].w, v1[i].w, hw[3], lw[3]);
                *reinterpret_cast<uint4*>(&pBhi[k2g * 136 + bn0]) =
                    make_uint4(hw[0], hw[1], hw[2], hw[3]);
                *reinterpret_cast<uint4*>(&pBlo[k2g * 136 + bn0]) =
                    make_uint4(lw[0], lw[1], lw[2], lw[3]);
            }
        }
    };

    auto compute = [&](int buf) {
        uint8_t* base = smem_raw + buf * SBUF;
        const __nv_bfloat16* pAhi = reinterpret_cast<const __nv_bfloat16*>(base);
        const __nv_bfloat16* pAlo = reinterpret_cast<const __nv_bfloat16*>(base + SOFF_ALO);
        const uint32_t* pBhi = reinterpret_cast<const uint32_t*>(base + SOFF_BHI);
        const uint32_t* pBlo = reinterpret_cast<const uint32_t*>(base + SOFF_BLO);

#pragma unroll
        for (int ks = 0; ks < 2; ks++) {
            uint32_t bh[4][2], bl[4][2];
#pragma unroll
            for (int ni = 0; ni < 4; ni++) {
                int wi = (tig + 8 * ks) * 136 + nw + 8 * ni + gid;
                bh[ni][0] = pBhi[wi]; bh[ni][1] = pBhi[wi + 544];
                bl[ni][0] = pBlo[wi]; bl[ni][1] = pBlo[wi + 544];
            }
#pragma unroll
            for (int mi = 0; mi < 4; mi++) {
                int o = (mw + 16 * mi + gid) * 40 + 16 * ks + 2 * tig;
                uint32_t ah0 = *reinterpret_cast<const uint32_t*>(pAhi + o);
                uint32_t ah1 = *reinterpret_cast<const uint32_t*>(pAhi + o + 320);
                uint32_t ah2 = *reinterpret_cast<const uint32_t*>(pAhi + o + 8);
                uint32_t ah3 = *reinterpret_cast<const uint32_t*>(pAhi + o + 328);
                uint32_t al0 = *reinterpret_cast<const uint32_t*>(pAlo + o);
                uint32_t al1 = *reinterpret_cast<const uint32_t*>(pAlo + o + 320);
                uint32_t al2 = *reinterpret_cast<const uint32_t*>(pAlo + o + 8);
                uint32_t al3 = *reinterpret_cast<const uint32_t*>(pAlo + o + 328);
#pragma unroll
                for (int ni = 0; ni < 4; ni++) {
                    MMA_BF16(acc[mi][ni], ah0, ah1, ah2, ah3, bh[ni][0], bh[ni][1]);
                    MMA_BF16(acc[mi][ni], ah0, ah1, ah2, ah3, bl[ni][0], bl[ni][1]);
                    MMA_BF16(acc[mi][ni], al0, al1, al2, al3, bh[ni][0], bh[ni][1]);
                }
            }
        }
    };

    fetch(0);
    store(0);
    __syncthreads();
    for (int t = 0; t < nT; t++) {
        const int cur = t & 1;
        const bool more = (t + 1 < nT);
        if (more) fetch((t + 1) << 5);
        compute(cur);
        if (more) {
            store(cur ^ 1);
            __syncthreads();
        }
    }

    // ---- epilogue ----
#pragma unroll
    for (int mi = 0; mi < 4; mi++) {
        int m0 = rowT + mw + 16 * mi + gid;
        float bi0 = 0.f, bi1 = 0.f, rs0 = 0.f, rb0 = 0.f, rs1 = 0.f, rb1 = 0.f;
        if (EP == EP_PERM_OUT) {
            rs0 = g_s2[m0]; rb0 = g_b2[m0];
            rs1 = g_s2[m0 + 8]; rb1 = g_b2[m0 + 8];
        } else { bi0 = bias[m0]; bi1 = bias[m0 + 8]; }
#pragma unroll
        for (int ni = 0; ni < 4; ni++) {
            int c0 = colT + nw + 8 * ni + 2 * tig;
            float e0 = acc[mi][ni][0], e1 = acc[mi][ni][1];
            float e2 = acc[mi][ni][2], e3 = acc[mi][ni][3];
            if (EP == EP_PERM_OUT) {
                e0 = e0 * rs0 + rb0; e1 = e1 * rs0 + rb0;
                e2 = e2 * rs1 + rb1; e3 = e3 * rs1 + rb1;
            } else {
                e0 += bi0; e1 += bi0; e2 += bi1; e3 += bi1;
            }
            if (EP == EP_LEAKY_H) {
                e0 = (e0 > 0.f) ? e0 : 0.1f * e0; e1 = (e1 > 0.f) ? e1 : 0.1f * e1;
                e2 = (e2 > 0.f) ? e2 : 0.1f * e2; e3 = (e3 > 0.f) ? e3 : 0.1f * e3;
                uint32_t h01, l01, h23, l23;
                split2(e0, e1, h01, l01);
                split2(e2, e3, h23, l23);
                size_t o0 = ((size_t)b * FF_ + m0) * HWN + c0;
                size_t o1 = ((size_t)b * FF_ + m0 + 8) * HWN + c0;
                *reinterpret_cast<uint32_t*>(g_hhi + o0) = h01;
                *reinterpret_cast<uint32_t*>(g_hlo + o0) = l01;
                *reinterpret_cast<uint32_t*>(g_hhi + o1) = h23;
                *reinterpret_cast<uint32_t*>(g_hlo + o1) = l23;
            } else if (EP == EP_PERM_P) {
                float vv[4] = {e0, e1, e2, e3};
#pragma unroll
                for (int q = 0; q < 4; q++) {
                    int m = m0 + (q >> 1) * 8;
                    int col = c0 + (q & 1);
                    int h = col >> 6, w = col & 63;
                    int pc = ((((h & 1) << 1) | (w & 1)) << 10) | ((h >> 1) << 5) | (w >> 1);
                    Y[((size_t)b * M + m) * HWN + pc] = vv[q];
                }
            } else if (EP == EP_PERM_OUT) {
                float vv[4] = {e0, e1, e2, e3};
#pragma unroll
                for (int q = 0; q < 4; q++) {
                    int m = m0 + (q >> 1) * 8;
                    int col = c0 + (q & 1);
                    int pq = col >> 10, n = col & 1023;
                    int h = ((n >> 5) << 1) | (pq >> 1);
                    int w = ((n & 31) << 1) | (pq & 1);
                    Y[((size_t)b * M + m) * HWN + h * 64 + w] = vv[q];
                }
            } else {
                float2* y0 = reinterpret_cast<float2*>(&Y[((size_t)b * M + m0) * HWN + c0]);
                float2* y1 = reinterpret_cast<float2*>(&Y[((size_t)b * M + m0 + 8) * HWN + c0]);
                if (EP == EP_RESID) {
                    float2 o0 = *y0, o1 = *y1;
                    o0.x += e0; o0.y += e1; o1.x += e2; o1.y += e3;
                    *y0 = o0; *y1 = o1;
                } else {
                    *y0 = make_float2(e0, e1);
                    *y1 = make_float2(e2, e3);
                }
            }
        }
    }
}

// ---------------- host ----------------
template<int BT, int EP>
static void launch_gemm(int woff, const float* Xf,
                        const __nv_bfloat16* Bh, const __nv_bfloat16* Bl,
                        float* Y, const float* bias, int M, int K, long strideB)
{
    cudaFuncSetAttribute(gemm_tc<BT, EP>,
                         cudaFuncAttributeMaxDynamicSharedMemorySize, SMEM_DYN);
    gemm_tc<BT, EP><<<dim3(32, M / 128, BB), 256, SMEM_DYN>>>(
        woff, Xf, Bh, Bl, Y, bias, M, K, strideB);
}

extern "C" void kernel_launch(void* const* d_in, const int* in_sizes, int n_in,
                              void* d_out, int out_size)
{
    const float* x     = (const float*)d_in[0];
    const float* dw_w  = (const float*)d_in[1];
    const float* bn1_g = (const float*)d_in[2];
    const float* bn1_b = (const float*)d_in[3];
    const float* bn1_m = (const float*)d_in[4];
    const float* bn1_v = (const float*)d_in[5];
    const float* c1_w  = (const float*)d_in[6];
    const float* c1_b  = (const float*)d_in[7];
    const float* ln1_g = (const float*)d_in[8];
    const float* ln1_b = (const float*)d_in[9];
    const float* qkv_w = (const float*)d_in[10];
    const float* qkv_b = (const float*)d_in[11];
    const float* out_w = (const float*)d_in[12];
    const float* out_b = (const float*)d_in[13];
    const float* ln2_g = (const float*)d_in[14];
    const float* ln2_b = (const float*)d_in[15];
    const float* f1_w  = (const float*)d_in[16];
    const float* f1_b  = (const float*)d_in[17];
    const float* f2_w  = (const float*)d_in[18];
    const float* f2_b  = (const float*)d_in[19];
    const float* lnf_g = (const float*)d_in[20];
    const float* lnf_b = (const float*)d_in[21];
    const float* projw = (const float*)d_in[22];
    const float* bn2_g = (const float*)d_in[23];
    const float* bn2_b = (const float*)d_in[24];
    const float* bn2_m = (const float*)d_in[25];
    const float* bn2_v = (const float*)d_in[26];
    float* out = (float*)d_out;

    void *vp;
    cudaGetSymbolAddress(&vp, g_p);   float* p  = (float*)vp;
    cudaGetSymbolAddress(&vp, g_kv);  float* kv = (float*)vp;
    cudaGetSymbolAddress(&vp, g_zhi); __nv_bfloat16* zhi = (__nv_bfloat16*)vp;
    cudaGetSymbolAddress(&vp, g_zlo); __nv_bfloat16* zlo = (__nv_bfloat16*)vp;
    cudaGetSymbolAddress(&vp, g_hhi); __nv_bfloat16* hhi = (__nv_bfloat16*)vp;
    cudaGetSymbolAddress(&vp, g_hlo); __nv_bfloat16* hlo = (__nv_bfloat16*)vp;
    cudaGetSymbolAddress(&vp, g_yhi); __nv_bfloat16* yhi = (__nv_bfloat16*)vp;
    cudaGetSymbolAddress(&vp, g_ylo); __nv_bfloat16* ylo = (__nv_bfloat16*)vp;

    prep_k<<<1, 128>>>(bn2_g, bn2_b, bn2_m, bn2_v);

    wsplit_k<<<(32768 + 255) / 256, 256>>>(c1_w, 32768, OFF_C1);
    for (int l = 0; l < 2; l++) {
        const float* qw = qkv_w + (size_t)l * 513 * DD;
        wsplit_k<<<(131072 + 255) / 256, 256>>>(qw + DD, 131072, OFF_KV(l));
        wsplit_k<<<(65536  + 255) / 256, 256>>>(out_w + (size_t)l * DD * DD, 65536, OFF_OUT(l));
        wsplit_k<<<(131072 + 255) / 256, 256>>>(f1_w + (size_t)l * FF_ * DD, 131072, OFF_F1(l));
        wsplit_k<<<(131072 + 255) / 256, 256>>>(f2_w + (size_t)l * DD * FF_, 131072, OFF_F2(l));
    }
    wsplit_k<<<(32768 + 255) / 256, 256>>>(projw, 32768, OFF_PROJ);

    dwconv_k<<<dim3(16, CC, BB), 256>>>(x, dw_w, bn1_g, bn1_b, bn1_m, bn1_v);

    // c1: 128->256, patchify-permuted store into p (B = pre-split y)
    launch_gemm<BT_PRE, EP_PERM_P>(OFF_C1, nullptr, yhi, ylo, p, c1_b,
                                   DD, CC, (long)CC * HWN);

    for (int l = 0; l < 2; l++) {
        const float* qw  = qkv_w + (size_t)l * 513 * DD;
        const float* qbi = qkv_b + l * 513;

        colstats_z_k<<<dim3(128, BB), dim3(32, 8)>>>(p, ln1_g + l * DD, ln1_b + l * DD);

        // kv = W_kv @ z
        launch_gemm<BT_PRE, EP_STORE>(OFF_KV(l), nullptr, zhi, zlo, kv, qbi + 1,
                                      512, DD, (long)DD * HWN);

        // q + softmax + ctx (reads z, k)
        qsoftctx_k<<<128, 256>>>(qw, qbi);

        // attn = out_w @ (relu(v)*ctx) + out_b ; p += attn
        launch_gemm<BT_V, EP_RESID>(OFF_OUT(l), kv + (size_t)DD * HWN, nullptr, nullptr,
                                    p, out_b + l * DD, DD, DD, (long)512 * HWN);

        colstats_z_k<<<dim3(128, BB), dim3(32, 8)>>>(p, ln2_g + l * DD, ln2_b + l * DD);

        // h = leaky(f1 @ z + b1) -> bf16 hi/lo
        launch_gemm<BT_PRE, EP_LEAKY_H>(OFF_F1(l), nullptr, zhi, zlo, nullptr,
                                        f1_b + l * FF_, FF_, DD, (long)DD * HWN);

        // p += f2 @ h + b2
        launch_gemm<BT_PRE, EP_RESID>(OFF_F2(l), nullptr, hhi, hlo, p,
                                      f2_b + l * DD, DD, FF_, (long)FF_ * HWN);
    }

    colstats_z_k<<<dim3(128, BB), dim3(32, 8)>>>(p, lnf_g, lnf_b);

    // out = BN2(proj @ zf), un-patchified spatial store
    launch_gemm<BT_PRE, EP_PERM_OUT>(OFF_PROJ, nullptr, zhi, zlo, out, nullptr,
                                     CC, DD, (long)DD * HWN);
}

// round 6
// speedup vs baseline: 1.9629x; 1.0001x over previous
#include <cuda_runtime.h>
#include <cuda_bf16.h>
#include <cstdint>

// ---------------- problem constants ----------------
#define BB   32
#define CC   128
#define HH   64
#define WW   64
#define DD   256
#define FF_  512
#define HWN  4096
#define EPS  1e-5f

// ---------------- static scratch ----------------
__device__ float g_p [ (size_t)BB * DD  * HWN ];   // 128 MB token tensor (fp32)
__device__ float g_kv[ (size_t)BB * 512 * HWN ];   // 256 MB k(0..255) v(256..511) fp32
__device__ float g_ctx [ BB * 4 * DD ];
__device__ float g_s2[CC], g_b2[CC];

// pre-split bf16 activations (hi/lo), row-major [b][row][4096]
__device__ __nv_bfloat16 g_zhi[(size_t)BB * DD  * HWN];   // 64 MB  LN output
__device__ __nv_bfloat16 g_zlo[(size_t)BB * DD  * HWN];
__device__ __nv_bfloat16 g_hhi[(size_t)BB * FF_ * HWN];   // 128 MB ffn hidden
__device__ __nv_bfloat16 g_hlo[(size_t)BB * FF_ * HWN];
__device__ __nv_bfloat16 g_yhi[(size_t)BB * CC  * HWN];   // 32 MB  dwconv out
__device__ __nv_bfloat16 g_ylo[(size_t)BB * CC  * HWN];

// split-bf16 weights (hi/lo)
#define WTOT 983040
__device__ __nv_bfloat16 g_whi[WTOT];
__device__ __nv_bfloat16 g_wlo[WTOT];

#define OFF_C1    0
#define LSTRIDE   458752
#define OFF_KV(l)  (32768 + (l) * LSTRIDE)
#define OFF_OUT(l) (OFF_KV(l) + 131072)
#define OFF_F1(l)  (OFF_KV(l) + 196608)
#define OFF_F2(l)  (OFF_KV(l) + 327680)
#define OFF_PROJ  (32768 + 2 * LSTRIDE)

// ---------------- prep ----------------
__global__ void prep_k(const float* __restrict__ g, const float* __restrict__ b,
                       const float* __restrict__ m, const float* __restrict__ v)
{
    int i = threadIdx.x;
    if (i < CC) {
        float s = g[i] * rsqrtf(v[i] + EPS);
        g_s2[i] = s;
        g_b2[i] = b[i] - m[i] * s;
    }
}

__global__ void wsplit_k(const float* __restrict__ src, int n, int off)
{
    int i = blockIdx.x * 256 + threadIdx.x;
    if (i < n) {
        float v = src[i];
        __nv_bfloat16 h = __float2bfloat16_rn(v);
        g_whi[off + i] = h;
        g_wlo[off + i] = __float2bfloat16_rn(v - __bfloat162float(h));
    }
}

// ---------------- dwconv3x3 + BN1 + leaky -> bf16 hi/lo ----------------
__global__ void __launch_bounds__(256) dwconv_k(
    const float* __restrict__ x, const float* __restrict__ w,
    const float* __restrict__ bg, const float* __restrict__ bbias,
    const float* __restrict__ bm, const float* __restrict__ bv)
{
    int b = blockIdx.z, c = blockIdx.y;
    int idx = blockIdx.x * 256 + threadIdx.x;
    __shared__ float ws[9];
    __shared__ float sc, sh;
    if (threadIdx.x < 9) ws[threadIdx.x] = w[c * 9 + threadIdx.x];
    if (threadIdx.x == 0) {
        float s = bg[c] * rsqrtf(bv[c] + EPS);
        sc = s; sh = bbias[c] - bm[c] * s;
    }
    __syncthreads();
    int h = idx >> 6, wq = idx & 63;
    const float* xp = x + ((size_t)b * CC + c) * HWN;
    float acc = 0.f;
#pragma unroll
    for (int dh = 0; dh < 3; dh++) {
        int hh = h + dh - 1;
        if (hh < 0 || hh >= HH) continue;
#pragma unroll
        for (int dw = 0; dw < 3; dw++) {
            int ww2 = wq + dw - 1;
            if (ww2 < 0 || ww2 >= WW) continue;
            acc = fmaf(xp[hh * 64 + ww2], ws[dh * 3 + dw], acc);
        }
    }
    float o = acc * sc + sh;
    o = (o > 0.f) ? o : 0.1f * o;
    size_t oidx = ((size_t)b * CC + c) * HWN + idx;
    __nv_bfloat16 hi = __float2bfloat16_rn(o);
    g_yhi[oidx] = hi;
    g_ylo[oidx] = __float2bfloat16_rn(o - __bfloat162float(hi));
}

// ---------------- colstats + LN -> z bf16 hi/lo ----------------
__global__ void __launch_bounds__(256) colstats_z_k(
    const float* __restrict__ p,
    const float* __restrict__ lng, const float* __restrict__ lnb)
{
    int b  = blockIdx.y;
    int tx = threadIdx.x, ty = threadIdx.y;
    int col = blockIdx.x * 32 + tx;
    int lt = ty * 32 + tx;

    __shared__ float sg[256], sb[256];
    sg[lt] = lng[lt]; sb[lt] = lnb[lt];

    size_t base = (size_t)b * DD * HWN + col;
    float vals[32];
    float s = 0.f, s2 = 0.f;
#pragma unroll
    for (int j = 0; j < 32; j++) {
        float v = p[base + ((size_t)(ty * 32 + j) << 12)];
        vals[j] = v; s += v; s2 = fmaf(v, v, s2);
    }
    __shared__ float sh1[8][32], sh2[8][32], smean[32], srstd[32];
    sh1[ty][tx] = s; sh2[ty][tx] = s2;
    __syncthreads();
    if (ty == 0) {
        float a = 0.f, a2 = 0.f;
#pragma unroll
        for (int k = 0; k < 8; k++) { a += sh1[k][tx]; a2 += sh2[k][tx]; }
        float mean = a * (1.f / DD);
        float var  = a2 * (1.f / DD) - mean * mean;
        smean[tx] = mean;
        srstd[tx] = rsqrtf(var + EPS);
    }
    __syncthreads();
    float mean = smean[tx], rstd = srstd[tx];
#pragma unroll
    for (int j = 0; j < 32; j++) {
        int d = ty * 32 + j;
        float z = (vals[j] - mean) * rstd * sg[d] + sb[d];
        __nv_bfloat16 hi = __float2bfloat16_rn(z);
        size_t o = base + ((size_t)d << 12);
        g_zhi[o] = hi;
        g_zlo[o] = __float2bfloat16_rn(z - __bfloat162float(hi));
    }
}

// ---------------- fused q-GEMV + softmax + ctx (reads pre-split z) ---------
__global__ void __launch_bounds__(256) qsoftctx_k(
    const float* __restrict__ wq, const float* __restrict__ qb)
{
    __shared__ float sprob[1024];
    __shared__ float wqs[256];
    __shared__ float red[256];
    int tid = threadIdx.x;
    int b = blockIdx.x >> 2, pq = blockIdx.x & 3;
    wqs[tid] = wq[tid];
    __syncthreads();
    size_t zbase = (size_t)b * DD * HWN + pq * 1024;
    float q0 = qb[0];
    float qv[4];
#pragma unroll
    for (int r = 0; r < 4; r++) {
        int n = tid + (r << 8);
        float acc = q0;
#pragma unroll 4
        for (int k = 0; k < 256; k++) {
            size_t o = zbase + ((size_t)k << 12) + n;
            float z = __bfloat162float(g_zhi[o]) + __bfloat162float(g_zlo[o]);
            acc = fmaf(wqs[k], z, acc);
        }
        qv[r] = acc;
    }
    float lm = fmaxf(fmaxf(qv[0], qv[1]), fmaxf(qv[2], qv[3]));
    red[tid] = lm; __syncthreads();
    for (int s = 128; s > 0; s >>= 1) { if (tid < s) red[tid] = fmaxf(red[tid], red[tid + s]); __syncthreads(); }
    float gm = red[0]; __syncthreads();
    float e[4]; float ls = 0.f;
#pragma unroll
    for (int r = 0; r < 4; r++) { e[r] = __expf(qv[r] - gm); ls += e[r]; }
    red[tid] = ls; __syncthreads();
    for (int s = 128; s > 0; s >>= 1) { if (tid < s) red[tid] += red[tid + s]; __syncthreads(); }
    float inv = 1.f / red[0];
#pragma unroll
    for (int r = 0; r < 4; r++) sprob[tid + (r << 8)] = e[r] * inv;
    __syncthreads();
    int warp = tid >> 5, lane = tid & 31;
    for (int d = warp; d < 256; d += 8) {
        const float* kr = g_kv + ((size_t)b * 512 + d) * HWN + pq * 1024;
        float acc = 0.f;
#pragma unroll 8
        for (int n = lane; n < 1024; n += 32) acc = fmaf(kr[n], sprob[n], acc);
#pragma unroll
        for (int o = 16; o > 0; o >>= 1) acc += __shfl_down_sync(0xffffffffu, acc, o);
        if (lane == 0) g_ctx[(b << 10) + (pq << 8) + d] = acc;
    }
}

// ---------------- tensor-core GEMM ----------------
enum { BT_PRE = 0, BT_V = 1 };
enum { EP_STORE = 0, EP_LEAKY_H = 1, EP_RESID = 2, EP_PERM_P = 3, EP_PERM_OUT = 4 };

__device__ __forceinline__ void split2(float a, float b, uint32_t& hi, uint32_t& lo)
{
    __nv_bfloat16 ha = __float2bfloat16_rn(a), hb = __float2bfloat16_rn(b);
    float ra = a - __bfloat162float(ha);
    float rb = b - __bfloat162float(hb);
    __nv_bfloat16 la = __float2bfloat16_rn(ra), lb = __float2bfloat16_rn(rb);
    hi = (uint32_t)__bfloat16_as_ushort(ha) | ((uint32_t)__bfloat16_as_ushort(hb) << 16);
    lo = (uint32_t)__bfloat16_as_ushort(la) | ((uint32_t)__bfloat16_as_ushort(lb) << 16);
}

#define MMA_BF16(D, A0, A1, A2, A3, B0, B1)                                   \
    asm volatile("mma.sync.aligned.m16n8k16.row.col.f32.bf16.bf16.f32 "       \
        "{%0,%1,%2,%3},{%4,%5,%6,%7},{%8,%9},{%0,%1,%2,%3};"                  \
        : "+f"((D)[0]), "+f"((D)[1]), "+f"((D)[2]), "+f"((D)[3])              \
        : "r"(A0), "r"(A1), "r"(A2), "r"(A3), "r"(B0), "r"(B1))

// smem buffer layout (bytes): Ahi 10240 | Alo 10240 | Bhi 8704 | Blo 8704
#define SBUF     37888
#define SOFF_ALO 10240
#define SOFF_BHI 20480
#define SOFF_BLO 29184
#define SMEM_DYN (2 * SBUF)

template<int BT, int EP>
__global__ void gemm_tc(int woff, const float* __restrict__ Xf,
                        const __nv_bfloat16* __restrict__ Bhg,
                        const __nv_bfloat16* __restrict__ Blg,
                        float* __restrict__ Y, const float* __restrict__ bias,
                        int M, int K, long strideB)
{
    extern __shared__ uint8_t smem_raw[];

    const int b    = blockIdx.z;
    const int colT = blockIdx.x * 128;
    const int rowT = blockIdx.y * 128;
    const float* Xp = (BT == BT_V) ? (Xf + (size_t)b * strideB + colT) : nullptr;
    const __nv_bfloat16* Bhp = (BT == BT_PRE) ? (Bhg + (size_t)b * strideB + colT) : nullptr;
    const __nv_bfloat16* Blp = (BT == BT_PRE) ? (Blg + (size_t)b * strideB + colT) : nullptr;
    const int ctxb = (b << 10) + ((colT >> 10) << 8);

    const int tid  = threadIdx.x;
    const int wid  = tid >> 5;
    const int lane = tid & 31;
    const int gid  = lane >> 2;
    const int tig  = lane & 3;
    const int mw   = (wid & 1) * 64;
    const int nw   = (wid >> 1) * 32;

    const int ar = tid >> 1, asg = tid & 1;
    const int bn0 = (tid & 31) * 4;

    float acc[4][4][4];
#pragma unroll
    for (int i = 0; i < 4; i++)
#pragma unroll
        for (int j = 0; j < 4; j++)
#pragma unroll
            for (int k = 0; k < 4; k++) acc[i][j][k] = 0.f;

    const int nT = K >> 5;

    uint4 aH[2], aL[2];
    float4 v0[2], v1[2];        // BT_V path
    uint4 bQH[2], bQL[2];       // BT_PRE path

    auto fetch = [&](int k0) {
        const uint4* sh = reinterpret_cast<const uint4*>(
            g_whi + woff + (size_t)(rowT + ar) * K + k0) + 2 * asg;
        const uint4* sl = reinterpret_cast<const uint4*>(
            g_wlo + woff + (size_t)(rowT + ar) * K + k0) + 2 * asg;
        aH[0] = sh[0]; aH[1] = sh[1];
        aL[0] = sl[0]; aL[1] = sl[1];
#pragma unroll
        for (int i = 0; i < 2; i++) {
            int k2g = wid + 8 * i;
            int kk  = k0 + 2 * k2g;
            if (BT == BT_PRE) {
                uint2 r0 = *reinterpret_cast<const uint2*>(Bhp + (size_t)kk * HWN + bn0);
                uint2 r1 = *reinterpret_cast<const uint2*>(Bhp + (size_t)(kk + 1) * HWN + bn0);
                bQH[i] = make_uint4(__byte_perm(r0.x, r1.x, 0x5410),
                                    __byte_perm(r0.x, r1.x, 0x7632),
                                    __byte_perm(r0.y, r1.y, 0x5410),
                                    __byte_perm(r0.y, r1.y, 0x7632));
                uint2 s0 = *reinterpret_cast<const uint2*>(Blp + (size_t)kk * HWN + bn0);
                uint2 s1 = *reinterpret_cast<const uint2*>(Blp + (size_t)(kk + 1) * HWN + bn0);
                bQL[i] = make_uint4(__byte_perm(s0.x, s1.x, 0x5410),
                                    __byte_perm(s0.x, s1.x, 0x7632),
                                    __byte_perm(s0.y, s1.y, 0x5410),
                                    __byte_perm(s0.y, s1.y, 0x7632));
            } else {
                v0[i] = reinterpret_cast<const float4*>(Xp + ((size_t)kk << 12))[lane];
                v1[i] = reinterpret_cast<const float4*>(Xp + ((size_t)(kk + 1) << 12))[lane];
                float c0v = g_ctx[ctxb + kk], c1v = g_ctx[ctxb + kk + 1];
                v0[i].x = fmaxf(v0[i].x, 0.f) * c0v; v0[i].y = fmaxf(v0[i].y, 0.f) * c0v;
                v0[i].z = fmaxf(v0[i].z, 0.f) * c0v; v0[i].w = fmaxf(v0[i].w, 0.f) * c0v;
                v1[i].x = fmaxf(v1[i].x, 0.f) * c1v; v1[i].y = fmaxf(v1[i].y, 0.f) * c1v;
                v1[i].z = fmaxf(v1[i].z, 0.f) * c1v; v1[i].w = fmaxf(v1[i].w, 0.f) * c1v;
            }
        }
    };

    auto store = [&](int buf) {
        uint8_t* base = smem_raw + buf * SBUF;
        __nv_bfloat16* pAhi = reinterpret_cast<__nv_bfloat16*>(base);
        __nv_bfloat16* pAlo = reinterpret_cast<__nv_bfloat16*>(base + SOFF_ALO);
        uint32_t* pBhi = reinterpret_cast<uint32_t*>(base + SOFF_BHI);
        uint32_t* pBlo = reinterpret_cast<uint32_t*>(base + SOFF_BLO);

        uint4* dh = reinterpret_cast<uint4*>(pAhi + ar * 40 + 16 * asg);
        dh[0] = aH[0]; dh[1] = aH[1];
        uint4* dl = reinterpret_cast<uint4*>(pAlo + ar * 40 + 16 * asg);
        dl[0] = aL[0]; dl[1] = aL[1];

#pragma unroll
        for (int i = 0; i < 2; i++) {
            int k2g = wid + 8 * i;
            if (BT == BT_PRE) {
                *reinterpret_cast<uint4*>(&pBhi[k2g * 136 + bn0]) = bQH[i];
                *reinterpret_cast<uint4*>(&pBlo[k2g * 136 + bn0]) = bQL[i];
            } else {
                uint32_t hw[4], lw[4];
                split2(v0[i].x, v1[i].x, hw[0], lw[0]);
                split2(v0[i].y, v1[i].y, hw[1], lw[1]);
                split2(v0[i].z, v1[i].z, hw[2], lw[2]);
                split2(v0[i].w, v1[i].w, hw[3], lw[3]);
                *reinterpret_cast<uint4*>(&pBhi[k2g * 136 + bn0]) =
                    make_uint4(hw[0], hw[1], hw[2], hw[3]);
                *reinterpret_cast<uint4*>(&pBlo[k2g * 136 + bn0]) =
                    make_uint4(lw[0], lw[1], lw[2], lw[3]);
            }
        }
    };

    auto compute = [&](int buf) {
        uint8_t* base = smem_raw + buf * SBUF;
        const __nv_bfloat16* pAhi = reinterpret_cast<const __nv_bfloat16*>(base);
        const __nv_bfloat16* pAlo = reinterpret_cast<const __nv_bfloat16*>(base + SOFF_ALO);
        const uint32_t* pBhi = reinterpret_cast<const uint32_t*>(base + SOFF_BHI);
        const uint32_t* pBlo = reinterpret_cast<const uint32_t*>(base + SOFF_BLO);

#pragma unroll
        for (int ks = 0; ks < 2; ks++) {
            uint32_t bh[4][2], bl[4][2];
#pragma unroll
            for (int ni = 0; ni < 4; ni++) {
                int wi = (tig + 8 * ks) * 136 + nw + 8 * ni + gid;
                bh[ni][0] = pBhi[wi]; bh[ni][1] = pBhi[wi + 544];
                bl[ni][0] = pBlo[wi]; bl[ni][1] = pBlo[wi + 544];
            }
#pragma unroll
            for (int mi = 0; mi < 4; mi++) {
                int o = (mw + 16 * mi + gid) * 40 + 16 * ks + 2 * tig;
                uint32_t ah0 = *reinterpret_cast<const uint32_t*>(pAhi + o);
                uint32_t ah1 = *reinterpret_cast<const uint32_t*>(pAhi + o + 320);
                uint32_t ah2 = *reinterpret_cast<const uint32_t*>(pAhi + o + 8);
                uint32_t ah3 = *reinterpret_cast<const uint32_t*>(pAhi + o + 328);
                uint32_t al0 = *reinterpret_cast<const uint32_t*>(pAlo + o);
                uint32_t al1 = *reinterpret_cast<const uint32_t*>(pAlo + o + 320);
                uint32_t al2 = *reinterpret_cast<const uint32_t*>(pAlo + o + 8);
                uint32_t al3 = *reinterpret_cast<const uint32_t*>(pAlo + o + 328);
#pragma unroll
                for (int ni = 0; ni < 4; ni++) {
                    MMA_BF16(acc[mi][ni], ah0, ah1, ah2, ah3, bh[ni][0], bh[ni][1]);
                    MMA_BF16(acc[mi][ni], ah0, ah1, ah2, ah3, bl[ni][0], bl[ni][1]);
                    MMA_BF16(acc[mi][ni], al0, al1, al2, al3, bh[ni][0], bh[ni][1]);
                }
            }
        }
    };

    fetch(0);
    store(0);
    __syncthreads();
    for (int t = 0; t < nT; t++) {
        const int cur = t & 1;
        const bool more = (t + 1 < nT);
        if (more) fetch((t + 1) << 5);
        compute(cur);
        if (more) {
            store(cur ^ 1);
            __syncthreads();
        }
    }

    // ---- epilogue ----
#pragma unroll
    for (int mi = 0; mi < 4; mi++) {
        int m0 = rowT + mw + 16 * mi + gid;
        float bi0 = 0.f, bi1 = 0.f, rs0 = 0.f, rb0 = 0.f, rs1 = 0.f, rb1 = 0.f;
        if (EP == EP_PERM_OUT) {
            rs0 = g_s2[m0]; rb0 = g_b2[m0];
            rs1 = g_s2[m0 + 8]; rb1 = g_b2[m0 + 8];
        } else { bi0 = bias[m0]; bi1 = bias[m0 + 8]; }
#pragma unroll
        for (int ni = 0; ni < 4; ni++) {
            int c0 = colT + nw + 8 * ni + 2 * tig;
            float e0 = acc[mi][ni][0], e1 = acc[mi][ni][1];
            float e2 = acc[mi][ni][2], e3 = acc[mi][ni][3];
            if (EP == EP_PERM_OUT) {
                e0 = e0 * rs0 + rb0; e1 = e1 * rs0 + rb0;
                e2 = e2 * rs1 + rb1; e3 = e3 * rs1 + rb1;
            } else {
                e0 += bi0; e1 += bi0; e2 += bi1; e3 += bi1;
            }
            if (EP == EP_LEAKY_H) {
                e0 = (e0 > 0.f) ? e0 : 0.1f * e0; e1 = (e1 > 0.f) ? e1 : 0.1f * e1;
                e2 = (e2 > 0.f) ? e2 : 0.1f * e2; e3 = (e3 > 0.f) ? e3 : 0.1f * e3;
                uint32_t h01, l01, h23, l23;
                split2(e0, e1, h01, l01);
                split2(e2, e3, h23, l23);
                size_t o0 = ((size_t)b * FF_ + m0) * HWN + c0;
                size_t o1 = ((size_t)b * FF_ + m0 + 8) * HWN + c0;
                *reinterpret_cast<uint32_t*>(g_hhi + o0) = h01;
                *reinterpret_cast<uint32_t*>(g_hlo + o0) = l01;
                *reinterpret_cast<uint32_t*>(g_hhi + o1) = h23;
                *reinterpret_cast<uint32_t*>(g_hlo + o1) = l23;
            } else if (EP == EP_PERM_P) {
                float vv[4] = {e0, e1, e2, e3};
#pragma unroll
                for (int q = 0; q < 4; q++) {
                    int m = m0 + (q >> 1) * 8;
                    int col = c0 + (q & 1);
                    int h = col >> 6, w = col & 63;
                    int pc = ((((h & 1) << 1) | (w & 1)) << 10) | ((h >> 1) << 5) | (w >> 1);
                    Y[((size_t)b * M + m) * HWN + pc] = vv[q];
                }
            } else if (EP == EP_PERM_OUT) {
                float vv[4] = {e0, e1, e2, e3};
#pragma unroll
                for (int q = 0; q < 4; q++) {
                    int m = m0 + (q >> 1) * 8;
                    int col = c0 + (q & 1);
                    int pq = col >> 10, n = col & 1023;
                    int h = ((n >> 5) << 1) | (pq >> 1);
                    int w = ((n & 31) << 1) | (pq & 1);
                    Y[((size_t)b * M + m) * HWN + h * 64 + w] = vv[q];
                }
            } else {
                float2* y0 = reinterpret_cast<float2*>(&Y[((size_t)b * M + m0) * HWN + c0]);
                float2* y1 = reinterpret_cast<float2*>(&Y[((size_t)b * M + m0 + 8) * HWN + c0]);
                if (EP == EP_RESID) {
                    float2 o0 = *y0, o1 = *y1;
                    o0.x += e0; o0.y += e1; o1.x += e2; o1.y += e3;
                    *y0 = o0; *y1 = o1;
                } else {
                    *y0 = make_float2(e0, e1);
                    *y1 = make_float2(e2, e3);
                }
            }
        }
    }
}

// ---------------- host ----------------
template<int BT, int EP>
static void launch_gemm(int woff, const float* Xf,
                        const __nv_bfloat16* Bh, const __nv_bfloat16* Bl,
                        float* Y, const float* bias, int M, int K, long strideB)
{
    cudaFuncSetAttribute(gemm_tc<BT, EP>,
                         cudaFuncAttributeMaxDynamicSharedMemorySize, SMEM_DYN);
    gemm_tc<BT, EP><<<dim3(32, M / 128, BB), 256, SMEM_DYN>>>(
        woff, Xf, Bh, Bl, Y, bias, M, K, strideB);
}

extern "C" void kernel_launch(void* const* d_in, const int* in_sizes, int n_in,
                              void* d_out, int out_size)
{
    const float* x     = (const float*)d_in[0];
    const float* dw_w  = (const float*)d_in[1];
    const float* bn1_g = (const float*)d_in[2];
    const float* bn1_b = (const float*)d_in[3];
    const float* bn1_m = (const float*)d_in[4];
    const float* bn1_v = (const float*)d_in[5];
    const float* c1_w  = (const float*)d_in[6];
    const float* c1_b  = (const float*)d_in[7];
    const float* ln1_g = (const float*)d_in[8];
    const float* ln1_b = (const float*)d_in[9];
    const float* qkv_w = (const float*)d_in[10];
    const float* qkv_b = (const float*)d_in[11];
    const float* out_w = (const float*)d_in[12];
    const float* out_b = (const float*)d_in[13];
    const float* ln2_g = (const float*)d_in[14];
    const float* ln2_b = (const float*)d_in[15];
    const float* f1_w  = (const float*)d_in[16];
    const float* f1_b  = (const float*)d_in[17];
    const float* f2_w  = (const float*)d_in[18];
    const float* f2_b  = (const float*)d_in[19];
    const float* lnf_g = (const float*)d_in[20];
    const float* lnf_b = (const float*)d_in[21];
    const float* projw = (const float*)d_in[22];
    const float* bn2_g = (const float*)d_in[23];
    const float* bn2_b = (const float*)d_in[24];
    const float* bn2_m = (const float*)d_in[25];
    const float* bn2_v = (const float*)d_in[26];
    float* out = (float*)d_out;

    void *vp;
    cudaGetSymbolAddress(&vp, g_p);   float* p  = (float*)vp;
    cudaGetSymbolAddress(&vp, g_kv);  float* kv = (float*)vp;
    cudaGetSymbolAddress(&vp, g_zhi); __nv_bfloat16* zhi = (__nv_bfloat16*)vp;
    cudaGetSymbolAddress(&vp, g_zlo); __nv_bfloat16* zlo = (__nv_bfloat16*)vp;
    cudaGetSymbolAddress(&vp, g_hhi); __nv_bfloat16* hhi = (__nv_bfloat16*)vp;
    cudaGetSymbolAddress(&vp, g_hlo); __nv_bfloat16* hlo = (__nv_bfloat16*)vp;
    cudaGetSymbolAddress(&vp, g_yhi); __nv_bfloat16* yhi = (__nv_bfloat16*)vp;
    cudaGetSymbolAddress(&vp, g_ylo); __nv_bfloat16* ylo = (__nv_bfloat16*)vp;

    prep_k<<<1, 128>>>(bn2_g, bn2_b, bn2_m, bn2_v);

    wsplit_k<<<(32768 + 255) / 256, 256>>>(c1_w, 32768, OFF_C1);
    for (int l = 0; l < 2; l++) {
        const float* qw = qkv_w + (size_t)l * 513 * DD;
        wsplit_k<<<(131072 + 255) / 256, 256>>>(qw + DD, 131072, OFF_KV(l));
        wsplit_k<<<(65536  + 255) / 256, 256>>>(out_w + (size_t)l * DD * DD, 65536, OFF_OUT(l));
        wsplit_k<<<(131072 + 255) / 256, 256>>>(f1_w + (size_t)l * FF_ * DD, 131072, OFF_F1(l));
        wsplit_k<<<(131072 + 255) / 256, 256>>>(f2_w + (size_t)l * DD * FF_, 131072, OFF_F2(l));
    }
    wsplit_k<<<(32768 + 255) / 256, 256>>>(projw, 32768, OFF_PROJ);

    dwconv_k<<<dim3(16, CC, BB), 256>>>(x, dw_w, bn1_g, bn1_b, bn1_m, bn1_v);

    // c1: 128->256, patchify-permuted store into p (B = pre-split y)
    launch_gemm<BT_PRE, EP_PERM_P>(OFF_C1, nullptr, yhi, ylo, p, c1_b,
                                   DD, CC, (long)CC * HWN);

    for (int l = 0; l < 2; l++) {
        const float* qw  = qkv_w + (size_t)l * 513 * DD;
        const float* qbi = qkv_b + l * 513;

        colstats_z_k<<<dim3(128, BB), dim3(32, 8)>>>(p, ln1_g + l * DD, ln1_b + l * DD);

        // kv = W_kv @ z
        launch_gemm<BT_PRE, EP_STORE>(OFF_KV(l), nullptr, zhi, zlo, kv, qbi + 1,
                                      512, DD, (long)DD * HWN);

        // q + softmax + ctx (reads z, k)
        qsoftctx_k<<<128, 256>>>(qw, qbi);

        // attn = out_w @ (relu(v)*ctx) + out_b ; p += attn
        launch_gemm<BT_V, EP_RESID>(OFF_OUT(l), kv + (size_t)DD * HWN, nullptr, nullptr,
                                    p, out_b + l * DD, DD, DD, (long)512 * HWN);

        colstats_z_k<<<dim3(128, BB), dim3(32, 8)>>>(p, ln2_g + l * DD, ln2_b + l * DD);

        // h = leaky(f1 @ z + b1) -> bf16 hi/lo
        launch_gemm<BT_PRE, EP_LEAKY_H>(OFF_F1(l), nullptr, zhi, zlo, nullptr,
                                        f1_b + l * FF_, FF_, DD, (long)DD * HWN);

        // p += f2 @ h + b2
        launch_gemm<BT_PRE, EP_RESID>(OFF_F2(l), nullptr, hhi, hlo, p,
                                      f2_b + l * DD, DD, FF_, (long)FF_ * HWN);
    }

    colstats_z_k<<<dim3(128, BB), dim3(32, 8)>>>(p, lnf_g, lnf_b);

    // out = BN2(proj @ zf), un-patchified spatial store
    launch_gemm<BT_PRE, EP_PERM_OUT>(OFF_PROJ, nullptr, zhi, zlo, out, nullptr,
                                     CC, DD, (long)DD * HWN);
}